// round 13
// baseline (speedup 1.0000x reference)
#include <cuda_runtime.h>
#include <math.h>
#include <stdint.h>

#define BB 4
#define SS 2048
#define HH 768
#define NH 12
#define DD 64
#define M_TOT (BB*SS)      /* 8192 */
#define N4H (4*HH)         /* 3072 */

typedef unsigned long long u64;

// ---------------- scratch (static device globals; proven delta=0) -----------
__device__ float g_proj[(size_t)M_TOT * N4H];      // [8192][3072] : U|V|Q|K
__device__ float g_Qt[(size_t)BB*NH*DD*SS];        // [bh][d][s] (pre-scaled)
__device__ float g_Kt[(size_t)BB*NH*DD*SS];        // [bh][d][s]
__device__ float g_V [(size_t)BB*NH*SS*DD];        // [bh][s][d]
__device__ float g_attn[(size_t)M_TOT * HH];       // [8192][768]
__device__ float g_gated[(size_t)M_TOT * HH];      // [8192][768]
__device__ float g_cos[SS*DD];
__device__ float g_sin[SS*DD];

// ---------------- packed f32x2 helpers (Blackwell FFMA2) --------------------
#define PACK2(u, lo, hi) \
    asm("mov.b64 %0, {%1, %2};" : "=l"(u) : "f"(lo), "f"(hi))
#define UNPACK2(lo, hi, u) \
    asm("mov.b64 {%0, %1}, %2;" : "=f"(lo), "=f"(hi) : "l"(u))
#define FMA2(d, a, b) \
    asm("fma.rn.f32x2 %0, %1, %2, %0;" : "+l"(d) : "l"(a), "l"(b))

__device__ __forceinline__ float ex2f(float x) {
    float r; asm("ex2.approx.f32 %0, %1;" : "=f"(r) : "f"(x)); return r;
}

// cp.async helpers (16B)
__device__ __forceinline__ void cp16(void* dst_smem, const void* src) {
    uint32_t d = (uint32_t)__cvta_generic_to_shared(dst_smem);
    asm volatile("cp.async.cg.shared.global [%0], [%1], 16;\n" :: "r"(d), "l"(src));
}
#define CP_COMMIT()  asm volatile("cp.async.commit_group;\n" ::: "memory")
#define CP_WAIT0()   asm volatile("cp.async.wait_group 0;\n" ::: "memory")
#define CP_WAIT1G()  asm volatile("cp.async.wait_group 1;\n" ::: "memory")

// scale folded into Qt: 0.125 * log2(e)
#define Q_PRESCALE 0.18033688011112042f

// ---------------- RoPE tables ----------------
__global__ void rope_table_kernel() {
    int s = blockIdx.x;
    int d = threadIdx.x;          // 0..63
    int p = d & 31;
    double invd = pow(10000.0, -((double)(2 * p)) / 64.0);
    float theta = (float)s * (float)invd;     // fp32 quantized like reference
    float sn, cs;
    sincosf(theta, &sn, &cs);
    g_cos[s*DD + d] = cs;
    g_sin[s*DD + d] = sn;
}

// ---------------- fp32 tiled GEMM: zero-mov FMA2 inner loop ------------------
// A stored DUPLICATED in smem (broadcast loads), B pairs natural from float4.
// mode 0: A = Aext (x), C = g_proj          (proj GEMM)
// mode 1: A = g_gated, C = Cext, res added  (out GEMM)
__global__ void __launch_bounds__(256, 2) gemm_kernel(
    const float* __restrict__ Aext, const float* __restrict__ Bw,
    const float* __restrict__ bias, const float* __restrict__ res,
    float* __restrict__ Cext, int M, int N, int K, int mode)
{
    __shared__ float Asd[2][16][256];   // A duplicated: [kk][2r]=[2r+1]=a_r
    __shared__ float Bs[2][16][128];

    const float* A = mode ? g_gated : Aext;
    float* C       = mode ? Cext    : g_proj;

    const int bm = blockIdx.y * 128;
    const int bn = blockIdx.x * 128;
    const int tid = threadIdx.x;
    const int tx = tid & 15;          // col group
    const int ty = tid >> 4;          // row group

    const int ar = tid >> 2;          // 0..63
    const int ac = (tid & 3) << 2;    // 0,4,8,12
    const int br = tid >> 5;          // 0..7
    const int bc = (tid & 31) << 2;   // 0..124

    u64 acc2[8][4];                   // [row i][col-pair jp]
#pragma unroll
    for (int i = 0; i < 8; i++)
#pragma unroll
        for (int jp = 0; jp < 4; jp++) acc2[i][jp] = 0ull;

#define STAGE(s, va0, va1, vb0, vb1) do {                                       \
    *(float2*)&Asd[s][ac+0][2*ar]      = make_float2((va0).x, (va0).x);         \
    *(float2*)&Asd[s][ac+1][2*ar]      = make_float2((va0).y, (va0).y);         \
    *(float2*)&Asd[s][ac+2][2*ar]      = make_float2((va0).z, (va0).z);         \
    *(float2*)&Asd[s][ac+3][2*ar]      = make_float2((va0).w, (va0).w);         \
    *(float2*)&Asd[s][ac+0][2*(ar+64)] = make_float2((va1).x, (va1).x);         \
    *(float2*)&Asd[s][ac+1][2*(ar+64)] = make_float2((va1).y, (va1).y);         \
    *(float2*)&Asd[s][ac+2][2*(ar+64)] = make_float2((va1).z, (va1).z);         \
    *(float2*)&Asd[s][ac+3][2*(ar+64)] = make_float2((va1).w, (va1).w);         \
    *(float4*)&Bs[s][br][bc]   = (vb0);                                         \
    *(float4*)&Bs[s][br+8][bc] = (vb1);                                         \
} while (0)

    // prologue: chunk 0 -> buf 0
    {
        float4 a0 = *(const float4*)(A + (size_t)(bm + ar)      * K + ac);
        float4 a1 = *(const float4*)(A + (size_t)(bm + ar + 64) * K + ac);
        float4 b0 = *(const float4*)(Bw + (size_t)(br)     * N + bn + bc);
        float4 b1 = *(const float4*)(Bw + (size_t)(br + 8) * N + bn + bc);
        STAGE(0, a0, a1, b0, b1);
    }
    __syncthreads();

    const int T = K / 16;
    for (int t = 0; t < T; t++) {
        float4 na0, na1, nb0, nb1;
        const bool pre = (t + 1 < T);
        if (pre) {
            int k0 = (t + 1) * 16;
            na0 = *(const float4*)(A + (size_t)(bm + ar)      * K + k0 + ac);
            na1 = *(const float4*)(A + (size_t)(bm + ar + 64) * K + k0 + ac);
            nb0 = *(const float4*)(Bw + (size_t)(k0 + br)     * N + bn + bc);
            nb1 = *(const float4*)(Bw + (size_t)(k0 + br + 8) * N + bn + bc);
        }

        const float (*ASD)[256] = Asd[t & 1];
        const float (*BS)[128]  = Bs[t & 1];
#pragma unroll
        for (int kk = 0; kk < 16; kk++) {
            ulonglong2 b01 = *(const ulonglong2*)&BS[kk][tx*8];     // (b0,b1),(b2,b3)
            ulonglong2 b23 = *(const ulonglong2*)&BS[kk][tx*8 + 4]; // (b4,b5),(b6,b7)
            ulonglong2 aA = *(const ulonglong2*)&ASD[kk][ty*16];      // (a0,a0),(a1,a1)
            ulonglong2 aB = *(const ulonglong2*)&ASD[kk][ty*16 + 4];  // (a2,a2),(a3,a3)
            ulonglong2 aC = *(const ulonglong2*)&ASD[kk][ty*16 + 8];  // (a4,a4),(a5,a5)
            ulonglong2 aD = *(const ulonglong2*)&ASD[kk][ty*16 + 12]; // (a6,a6),(a7,a7)
            u64 ad0 = aA.x, ad1 = aA.y, ad2 = aB.x, ad3 = aB.y;
            u64 ad4 = aC.x, ad5 = aC.y, ad6 = aD.x, ad7 = aD.y;
            u64 bp0 = b01.x, bp1 = b01.y, bp2 = b23.x, bp3 = b23.y;
            FMA2(acc2[0][0], ad0, bp0); FMA2(acc2[0][1], ad0, bp1);
            FMA2(acc2[0][2], ad0, bp2); FMA2(acc2[0][3], ad0, bp3);
            FMA2(acc2[1][0], ad1, bp0); FMA2(acc2[1][1], ad1, bp1);
            FMA2(acc2[1][2], ad1, bp2); FMA2(acc2[1][3], ad1, bp3);
            FMA2(acc2[2][0], ad2, bp0); FMA2(acc2[2][1], ad2, bp1);
            FMA2(acc2[2][2], ad2, bp2); FMA2(acc2[2][3], ad2, bp3);
            FMA2(acc2[3][0], ad3, bp0); FMA2(acc2[3][1], ad3, bp1);
            FMA2(acc2[3][2], ad3, bp2); FMA2(acc2[3][3], ad3, bp3);
            FMA2(acc2[4][0], ad4, bp0); FMA2(acc2[4][1], ad4, bp1);
            FMA2(acc2[4][2], ad4, bp2); FMA2(acc2[4][3], ad4, bp3);
            FMA2(acc2[5][0], ad5, bp0); FMA2(acc2[5][1], ad5, bp1);
            FMA2(acc2[5][2], ad5, bp2); FMA2(acc2[5][3], ad5, bp3);
            FMA2(acc2[6][0], ad6, bp0); FMA2(acc2[6][1], ad6, bp1);
            FMA2(acc2[6][2], ad6, bp2); FMA2(acc2[6][3], ad6, bp3);
            FMA2(acc2[7][0], ad7, bp0); FMA2(acc2[7][1], ad7, bp1);
            FMA2(acc2[7][2], ad7, bp2); FMA2(acc2[7][3], ad7, bp3);
        }

        if (pre) {
            int s = (t + 1) & 1;
            STAGE(s, na0, na1, nb0, nb1);
            __syncthreads();
        }
    }

    // epilogue
#pragma unroll
    for (int i = 0; i < 8; i++) {
        int row = bm + ty*8 + i;
        int col = bn + tx*8;
        float4 oA, oB;
        UNPACK2(oA.x, oA.y, acc2[i][0]);
        UNPACK2(oA.z, oA.w, acc2[i][1]);
        UNPACK2(oB.x, oB.y, acc2[i][2]);
        UNPACK2(oB.z, oB.w, acc2[i][3]);
        float4 bva = *(const float4*)(bias + col);
        float4 bvb = *(const float4*)(bias + col + 4);
        oA.x += bva.x; oA.y += bva.y; oA.z += bva.z; oA.w += bva.w;
        oB.x += bvb.x; oB.y += bvb.y; oB.z += bvb.z; oB.w += bvb.w;
        if (mode) {
            float4 ra = *(const float4*)(res + (size_t)row * N + col);
            float4 rb = *(const float4*)(res + (size_t)row * N + col + 4);
            oA.x += ra.x; oA.y += ra.y; oA.z += ra.z; oA.w += ra.w;
            oB.x += rb.x; oB.y += rb.y; oB.z += rb.z; oB.w += rb.w;
        }
        *(float4*)(C + (size_t)row * N + col)     = oA;
        *(float4*)(C + (size_t)row * N + col + 4) = oB;
    }
}

// ---------------- RoPE + layout transform (Q pre-scaled) ----------------
__global__ void __launch_bounds__(256) rope_kernel()
{
    __shared__ float sq[64][65];
    __shared__ float sk[64][65];

    const int bh = blockIdx.y;
    const int b  = bh / NH;
    const int h  = bh % NH;
    const int s0 = blockIdx.x * 64;
    const int tid = threadIdx.x;
    const int d4 = (tid & 15) * 4;   // 0..60
    const int r0 = tid >> 4;         // 0..15

#pragma unroll
    for (int rep = 0; rep < 4; rep++) {
        int sl = r0 + rep * 16;
        int s  = s0 + sl;
        size_t base = ((size_t)(b * SS + s)) * N4H + h * DD;
        float4 q  = *(const float4*)(g_proj + base + 2*HH + d4);
        float4 k  = *(const float4*)(g_proj + base + 3*HH + d4);
        float4 v  = *(const float4*)(g_proj + base +   HH + d4);
        int dp = (d4 < 32) ? d4 + 32 : d4 - 32;
        float sgn = (d4 < 32) ? -1.f : 1.f;
        float4 qp = *(const float4*)(g_proj + base + 2*HH + dp);
        float4 kp = *(const float4*)(g_proj + base + 3*HH + dp);
        float4 cs = *(const float4*)(g_cos + s*DD + d4);
        float4 sn = *(const float4*)(g_sin + s*DD + d4);

        *(float4*)(g_V + ((size_t)bh * SS + s) * DD + d4) = v;

        sq[d4+0][sl] = q.x * cs.x + sgn * qp.x * sn.x;
        sq[d4+1][sl] = q.y * cs.y + sgn * qp.y * sn.y;
        sq[d4+2][sl] = q.z * cs.z + sgn * qp.z * sn.z;
        sq[d4+3][sl] = q.w * cs.w + sgn * qp.w * sn.w;

        sk[d4+0][sl] = k.x * cs.x + sgn * kp.x * sn.x;
        sk[d4+1][sl] = k.y * cs.y + sgn * kp.y * sn.y;
        sk[d4+2][sl] = k.z * cs.z + sgn * kp.z * sn.z;
        sk[d4+3][sl] = k.w * cs.w + sgn * kp.w * sn.w;
    }
    __syncthreads();

#pragma unroll
    for (int rep = 0; rep < 4; rep++) {
        int drow = r0 + rep * 16;
        int s4 = d4;
        float4 oq, ok;
        oq.x = sq[drow][s4+0] * Q_PRESCALE;
        oq.y = sq[drow][s4+1] * Q_PRESCALE;
        oq.z = sq[drow][s4+2] * Q_PRESCALE;
        oq.w = sq[drow][s4+3] * Q_PRESCALE;
        ok.x = sk[drow][s4+0]; ok.y = sk[drow][s4+1]; ok.z = sk[drow][s4+2]; ok.w = sk[drow][s4+3];
        *(float4*)(g_Qt + ((size_t)bh * DD + drow) * SS + s0 + s4) = oq;
        *(float4*)(g_Kt + ((size_t)bh * DD + drow) * SS + s0 + s4) = ok;
    }
}

// ---------------- fused causal sigmoid attention: cp.async pipelined --------
// 128q x 64k tiles; K double-buffered via cp.async, V single-buffer cp.async
// hidden under QK. smem = Q 32K + K 2x16K + V 16K + ST 32K = 112KB -> 2 CTAs/SM.
#define ATTN_SMEM ((8192 + 2*4096 + 4096 + 8192) * 4)   /* 112KB */

__global__ void __launch_bounds__(256, 2) attn_kernel()
{
    extern __shared__ float smx[];
    float* Qs  = smx;                 // [64][128]  [d][q]
    float* Ks0 = smx + 8192;          // [64][64]   [d][k] buf 0
    float* Ks1 = smx + 12288;         // [64][64]   [d][k] buf 1
    float* Vs  = smx + 16384;         // [64][64]   [k][d]
    float* STs = smx + 20480;         // [64][128]  [k][q]  (swizzled)

    const int bh = blockIdx.y;
    const int qb = 15 - blockIdx.x;   // big CTAs first -> short tail
    const int tid = threadIdx.x;
    const int tx = tid & 15;
    const int ty = tid >> 4;

    // load Q tile [64][128] (plain; covered by first barrier)
#pragma unroll
    for (int i = 0; i < 8; i++) {
        int idx = tid + 256 * i;           // float4 index 0..2047
        int d = idx >> 5;
        int c = (idx & 31) << 2;
        *(float4*)(Qs + d * 128 + c) =
            *(const float4*)(g_Qt + ((size_t)bh * DD + d) * SS + qb * 128 + c);
    }

    // prologue: async K(0) -> buf0
#pragma unroll
    for (int i = 0; i < 4; i++) {
        int idx = tid + 256 * i;           // 1024 float4 = 64x64
        int d = idx >> 4;
        int c = (idx & 15) << 2;
        cp16(Ks0 + d * 64 + c,
             g_Kt + ((size_t)bh * DD + d) * SS + 0 * 64 + c);
    }
    CP_COMMIT();

    u64 o2[4][4];
#pragma unroll
    for (int i = 0; i < 4; i++)
#pragma unroll
        for (int d = 0; d < 4; d++) o2[i][d] = 0ull;

    const int ktmax = 2 * qb + 1;
    for (int kt = 0; kt <= ktmax; kt++) {
        float* Kcur = (kt & 1) ? Ks1 : Ks0;
        float* Knxt = (kt & 1) ? Ks0 : Ks1;

        CP_WAIT0();                  // K(kt) arrived (committed a phase ago)
        __syncthreads();             // K visible; prev SV reads of Vs/STs done

        // async V(kt) — consumed after QK+sigmoid (hidden)
#pragma unroll
        for (int i = 0; i < 4; i++) {
            int idx = tid + 256 * i;
            int k = idx >> 4;
            int c = (idx & 15) << 2;
            cp16(Vs + k * 64 + c,
                 g_V + ((size_t)bh * SS + kt * 64 + k) * DD + c);
        }
        CP_COMMIT();

        // async K(kt+1) — consumed next iteration
        if (kt < ktmax) {
#pragma unroll
            for (int i = 0; i < 4; i++) {
                int idx = tid + 256 * i;
                int d = idx >> 4;
                int c = (idx & 15) << 2;
                cp16(Knxt + d * 64 + c,
                     g_Kt + ((size_t)bh * DD + d) * SS + (kt + 1) * 64 + c);
            }
        }
        CP_COMMIT();

        // ---- QK^T: S fragment 8q(paired) x 4k over d=64 ----
        u64 s2[4][4];
#pragma unroll
        for (int i = 0; i < 4; i++)
#pragma unroll
            for (int j = 0; j < 4; j++) s2[i][j] = 0ull;

#pragma unroll 4
        for (int kk = 0; kk < 64; kk++) {
            float4 a0 = *(float4*)(Qs + kk * 128 + ty * 8);
            float4 a1 = *(float4*)(Qs + kk * 128 + ty * 8 + 4);
            float4 b0 = *(float4*)(Kcur + kk * 64 + tx * 4);
            u64 ap[4];
            PACK2(ap[0], a0.x, a0.y); PACK2(ap[1], a0.z, a0.w);
            PACK2(ap[2], a1.x, a1.y); PACK2(ap[3], a1.z, a1.w);
            u64 bd[4];
            PACK2(bd[0], b0.x, b0.x); PACK2(bd[1], b0.y, b0.y);
            PACK2(bd[2], b0.z, b0.z); PACK2(bd[3], b0.w, b0.w);
#pragma unroll
            for (int i = 0; i < 4; i++)
#pragma unroll
                for (int j = 0; j < 4; j++)
                    FMA2(s2[i][j], ap[i], bd[j]);
        }

        // ---- sigmoid + causal mask, store swizzled S^T[k][q] ----
        const bool diagzone = (kt >= 2 * qb);
        const int koff = (kt - 2 * qb) * 64;
#pragma unroll
        for (int j = 0; j < 4; j++) {
            int krow = tx * 4 + j;
#pragma unroll
            for (int i = 0; i < 4; i++) {
                float sa, sb;
                UNPACK2(sa, sb, s2[i][j]);
                float pa = __fdividef(1.f, 1.f + ex2f(-sa));
                float pb = __fdividef(1.f, 1.f + ex2f(-sb));
                if (diagzone) {
                    int qa = ty * 8 + 2 * i;
                    if (koff + krow > qa)     pa = 0.f;
                    if (koff + krow > qa + 1) pb = 0.f;
                }
                int c4s = (ty * 2 + (i >> 1)) ^ tx;
                float2 pv; pv.x = pa; pv.y = pb;
                *(float2*)(STs + krow * 128 + c4s * 4 + (i & 1) * 2) = pv;
            }
        }
        CP_WAIT1G();                 // V(kt) arrived (K(kt+1) may still fly)
        __syncthreads();             // STs + Vs visible

        // ---- S @ V: O fragment 8q(paired) x 4d over k=64 ----
#pragma unroll 4
        for (int t = 0; t < 64; t++) {
            int g = (t >> 2) & 15;
            float4 s0 = *(float4*)(STs + t * 128 + ((ty * 2)     ^ g) * 4);
            float4 s1 = *(float4*)(STs + t * 128 + ((ty * 2 + 1) ^ g) * 4);
            float4 vv = *(float4*)(Vs + t * 64 + tx * 4);
            u64 sp[4];
            PACK2(sp[0], s0.x, s0.y); PACK2(sp[1], s0.z, s0.w);
            PACK2(sp[2], s1.x, s1.y); PACK2(sp[3], s1.z, s1.w);
            u64 vd[4];
            PACK2(vd[0], vv.x, vv.x); PACK2(vd[1], vv.y, vv.y);
            PACK2(vd[2], vv.z, vv.z); PACK2(vd[3], vv.w, vv.w);
#pragma unroll
            for (int i = 0; i < 4; i++)
#pragma unroll
                for (int d = 0; d < 4; d++)
                    FMA2(o2[i][d], sp[i], vd[d]);
        }
    }

    // ---- epilogue ----
    const int b = bh / NH;
    const int h = bh % NH;
#pragma unroll
    for (int i = 0; i < 4; i++) {
        int q0 = qb * 128 + ty * 8 + 2 * i;
        float4 r0, r1;
        UNPACK2(r0.x, r1.x, o2[i][0]);
        UNPACK2(r0.y, r1.y, o2[i][1]);
        UNPACK2(r0.z, r1.z, o2[i][2]);
        UNPACK2(r0.w, r1.w, o2[i][3]);
        *(float4*)(g_attn + ((size_t)(b * SS + q0))     * HH + h * DD + tx * 4) = r0;
        *(float4*)(g_attn + ((size_t)(b * SS + q0 + 1)) * HH + h * DD + tx * 4) = r1;
    }
}

// ---------------- LayerNorm + SiLU gate (unchanged) ---------------
__device__ __forceinline__ float block_reduce_sum(float v, float* red)
{
    int lane = threadIdx.x & 31;
    int wid  = threadIdx.x >> 5;
#pragma unroll
    for (int o = 16; o > 0; o >>= 1) v += __shfl_xor_sync(0xffffffffu, v, o);
    if (lane == 0) red[wid] = v;
    __syncthreads();
    float r = (lane < 8) ? red[lane] : 0.f;
    if (wid == 0) {
#pragma unroll
        for (int o = 4; o > 0; o >>= 1) r += __shfl_xor_sync(0xffffffffu, r, o);
        if (lane == 0) red[0] = r;
    }
    __syncthreads();
    float out = red[0];
    __syncthreads();
    return out;
}

__global__ void __launch_bounds__(256) ln_gate_kernel(
    const float* __restrict__ gamma, const float* __restrict__ beta)
{
    __shared__ float sm[HH];
    __shared__ float red[32];
    const int row = blockIdx.x;
    const int tid = threadIdx.x;

    float loc = 0.f;
#pragma unroll
    for (int k = 0; k < 3; k++) {
        int i = tid + k * 256;
        float v = g_attn[(size_t)row * HH + i];
        sm[i] = v;
        loc += v;
    }
    float mu = block_reduce_sum(loc, red) * (1.f / HH);

    float loc2 = 0.f;
#pragma unroll
    for (int k = 0; k < 3; k++) {
        int i = tid + k * 256;
        float d = sm[i] - mu;
        loc2 += d * d;
    }
    float var = block_reduce_sum(loc2, red) * (1.f / HH);
    float rstd = rsqrtf(var + 1e-8f);

#pragma unroll
    for (int k = 0; k < 3; k++) {
        int i = tid + k * 256;
        float ln = (sm[i] - mu) * rstd * gamma[i] + beta[i];
        float u = g_proj[(size_t)row * N4H + i];   // U = first quarter
        float silu = __fdividef(u, 1.f + __expf(-u));
        g_gated[(size_t)row * HH + i] = silu * ln;
    }
}

// ---------------- launch ----------------
extern "C" void kernel_launch(void* const* d_in, const int* in_sizes, int n_in,
                              void* d_out, int out_size)
{
    const float* x      = (const float*)d_in[0];
    // d_in[1] = attn_mask (causal tril bool) — structure hardcoded
    const float* W_proj = (const float*)d_in[2];
    const float* b_proj = (const float*)d_in[3];
    const float* gamma  = (const float*)d_in[4];
    const float* beta   = (const float*)d_in[5];
    const float* W_out  = (const float*)d_in[6];
    const float* b_out  = (const float*)d_in[7];
    float* out = (float*)d_out;

    cudaFuncSetAttribute(attn_kernel,
        cudaFuncAttributeMaxDynamicSharedMemorySize, ATTN_SMEM);

    // 1. RoPE tables
    rope_table_kernel<<<SS, DD>>>();

    // 2. proj = x @ W_proj + b_proj   [8192,768]@[768,3072]
    gemm_kernel<<<dim3(N4H/128, M_TOT/128), 256>>>(
        x, W_proj, b_proj, nullptr, nullptr, M_TOT, N4H, HH, 0);

    // 3. RoPE + transpose into attention layouts
    rope_kernel<<<dim3(SS/64, BB*NH), 256>>>();

    // 4. fused causal sigmoid attention (cp.async pipelined)
    attn_kernel<<<dim3(SS/128, BB*NH), 256, ATTN_SMEM>>>();

    // 5. LayerNorm + SiLU(U) gate
    ln_gate_kernel<<<M_TOT, 256>>>(gamma, beta);

    // 6. out = residual + gated @ W_out + b_out
    gemm_kernel<<<dim3(HH/128, M_TOT/128), 256>>>(
        x, W_out, b_out, x, out, M_TOT, HH, HH, 1);
}

// round 15
// speedup vs baseline: 1.0879x; 1.0879x over previous
#include <cuda_runtime.h>
#include <math.h>
#include <stdint.h>

#define BB 4
#define SS 2048
#define HH 768
#define NH 12
#define DD 64
#define M_TOT (BB*SS)      /* 8192 */
#define N4H (4*HH)         /* 3072 */

typedef unsigned long long u64;

// ---------------- scratch (static device globals; referenced ONLY in-kernel) -
__device__ float g_proj[(size_t)M_TOT * N4H];      // [8192][3072] : U|V|Q|K
__device__ float g_Qt[(size_t)BB*NH*DD*SS];        // [bh][d][s] (pre-scaled)
__device__ float g_Kt[(size_t)BB*NH*DD*SS];        // [bh][d][s]
__device__ float g_V [(size_t)BB*NH*SS*DD];        // [bh][s][d]
__device__ float g_attn[(size_t)M_TOT * HH];       // [8192][768]; gated in-place
__device__ float g_WprojD[(size_t)(N4H/128) * HH * 256];  // dup'd W_proj tiles
__device__ float g_WoutD [(size_t)(HH/128)  * HH * 256];  // dup'd W_out tiles
__device__ float g_cos[SS*DD];
__device__ float g_sin[SS*DD];

// ---------------- packed f32x2 helpers (Blackwell FFMA2) --------------------
#define PACK2(u, lo, hi) \
    asm("mov.b64 %0, {%1, %2};" : "=l"(u) : "f"(lo), "f"(hi))
#define UNPACK2(lo, hi, u) \
    asm("mov.b64 {%0, %1}, %2;" : "=f"(lo), "=f"(hi) : "l"(u))
#define FMA2(d, a, b) \
    asm("fma.rn.f32x2 %0, %1, %2, %0;" : "+l"(d) : "l"(a), "l"(b))

__device__ __forceinline__ float ex2f(float x) {
    float r; asm("ex2.approx.f32 %0, %1;" : "=f"(r) : "f"(x)); return r;
}

// cp.async helpers (16B)
__device__ __forceinline__ void cp16(void* dst_smem, const void* src) {
    uint32_t d = (uint32_t)__cvta_generic_to_shared(dst_smem);
    asm volatile("cp.async.cg.shared.global [%0], [%1], 16;\n" :: "r"(d), "l"(src));
}
#define CP_COMMIT()  asm volatile("cp.async.commit_group;\n" ::: "memory")
#define CP_WAIT0()   asm volatile("cp.async.wait_group 0;\n" ::: "memory")
#define CP_WAIT1G()  asm volatile("cp.async.wait_group 1;\n" ::: "memory")

// scale folded into Qt: 0.125 * log2(e)
#define Q_PRESCALE 0.18033688011112042f

// ---------------- RoPE tables ----------------
__global__ void rope_table_kernel() {
    int s = blockIdx.x;
    int d = threadIdx.x;          // 0..63
    int p = d & 31;
    double invd = pow(10000.0, -((double)(2 * p)) / 64.0);
    float theta = (float)s * (float)invd;     // fp32 quantized like reference
    float sn, cs;
    sincosf(theta, &sn, &cs);
    g_cos[s*DD + d] = cs;
    g_sin[s*DD + d] = sn;
}

// ---------------- one-time weight duplication staging -----------------------
// BD[nb][k][q], q = jp*16 + tx (float4): (w0,w0,w1,w1), cols = nb*128+tx*8+2jp.
__global__ void dup_b_kernel(const float* __restrict__ W, int N, int which)
{
    float* BD = which ? g_WoutD : g_WprojD;
    size_t p = (size_t)blockIdx.x * 256 + threadIdx.x;     // float4 index
    size_t tot = (size_t)HH * (N >> 7) * 64;
    if (p >= tot) return;
    int q  = (int)(p & 63);
    size_t rk = p >> 6;
    int k  = (int)(rk % HH);
    int nb = (int)(rk / HH);
    int jp = q >> 4, tx = q & 15;
    int col = nb * 128 + tx * 8 + 2 * jp;
    float w0 = W[(size_t)k * N + col];
    float w1 = W[(size_t)k * N + col + 1];
    float4 o; o.x = w0; o.y = w0; o.z = w1; o.w = w1;
    ((float4*)BD)[((size_t)nb * HH + k) * 64 + q] = o;
}

// ---------------- fp32 tiled GEMM: zero-mov FMA2, dup'd-B in global ---------
// mode 0: A = Aext (x), BD = g_WprojD, C = g_proj
// mode 1: A = g_attn (gated), BD = g_WoutD, C = Cext, + res
__global__ void __launch_bounds__(256, 2) gemm_kernel(
    const float* __restrict__ Aext,
    const float* __restrict__ bias, const float* __restrict__ res,
    float* __restrict__ Cext, int N, int mode)
{
    __shared__ float As[2][16][128];
    __shared__ float Bsd[2][16][256];

    const float* A  = mode ? g_attn  : Aext;
    const float* BD = mode ? g_WoutD : g_WprojD;
    float* C        = mode ? Cext    : g_proj;

    const int bm = blockIdx.y * 128;
    const int nb = blockIdx.x;
    const int bn = nb * 128;
    const int tid = threadIdx.x;
    const int tx = tid & 15;          // col group
    const int ty = tid >> 4;          // row group

    const int ar = tid >> 2;          // 0..63
    const int ac = (tid & 3) << 2;    // 0,4,8,12
    const int K = HH;

    const float4* BDt = (const float4*)BD + (size_t)nb * HH * 64;

    u64 acc2[4][8];                   // [row-pair ip][col j]
#pragma unroll
    for (int ip = 0; ip < 4; ip++)
#pragma unroll
        for (int j = 0; j < 8; j++) acc2[ip][j] = 0ull;

#define STAGE15(s, va0, va1, vb) do {                                           \
    As[s][ac+0][ar] = (va0).x; As[s][ac+1][ar] = (va0).y;                       \
    As[s][ac+2][ar] = (va0).z; As[s][ac+3][ar] = (va0).w;                       \
    As[s][ac+0][ar+64] = (va1).x; As[s][ac+1][ar+64] = (va1).y;                 \
    As[s][ac+2][ar+64] = (va1).z; As[s][ac+3][ar+64] = (va1).w;                 \
    _Pragma("unroll")                                                           \
    for (int i = 0; i < 4; i++)                                                 \
        ((float4*)&Bsd[s][0][0])[tid + 256 * i] = (vb)[i];                      \
} while (0)

    // prologue: chunk 0 -> buf 0
    {
        float4 a0 = *(const float4*)(A + (size_t)(bm + ar)      * K + ac);
        float4 a1 = *(const float4*)(A + (size_t)(bm + ar + 64) * K + ac);
        float4 vb[4];
#pragma unroll
        for (int i = 0; i < 4; i++) vb[i] = BDt[tid + 256 * i];
        STAGE15(0, a0, a1, vb);
    }
    __syncthreads();

    const int T = K / 16;
    for (int t = 0; t < T; t++) {
        float4 na0, na1, nvb[4];
        const bool pre = (t + 1 < T);
        if (pre) {
            int k0 = (t + 1) * 16;
            na0 = *(const float4*)(A + (size_t)(bm + ar)      * K + k0 + ac);
            na1 = *(const float4*)(A + (size_t)(bm + ar + 64) * K + k0 + ac);
            const float4* src = BDt + (size_t)k0 * 64;
#pragma unroll
            for (int i = 0; i < 4; i++) nvb[i] = src[tid + 256 * i];
        }

        const float (*AS)[128]  = As[t & 1];
        const float (*BSD)[256] = Bsd[t & 1];
#pragma unroll
        for (int kk = 0; kk < 16; kk++) {
            ulonglong2 aA = *(const ulonglong2*)&AS[kk][ty*8];      // rows 0-1,2-3
            ulonglong2 aB = *(const ulonglong2*)&AS[kk][ty*8 + 4];  // rows 4-5,6-7
            ulonglong2 b0 = *(const ulonglong2*)&BSD[kk][tx*4];        // bd0,bd1
            ulonglong2 b1 = *(const ulonglong2*)&BSD[kk][64 + tx*4];   // bd2,bd3
            ulonglong2 b2 = *(const ulonglong2*)&BSD[kk][128 + tx*4];  // bd4,bd5
            ulonglong2 b3 = *(const ulonglong2*)&BSD[kk][192 + tx*4];  // bd6,bd7
            FMA2(acc2[0][0], aA.x, b0.x); FMA2(acc2[0][1], aA.x, b0.y);
            FMA2(acc2[0][2], aA.x, b1.x); FMA2(acc2[0][3], aA.x, b1.y);
            FMA2(acc2[0][4], aA.x, b2.x); FMA2(acc2[0][5], aA.x, b2.y);
            FMA2(acc2[0][6], aA.x, b3.x); FMA2(acc2[0][7], aA.x, b3.y);
            FMA2(acc2[1][0], aA.y, b0.x); FMA2(acc2[1][1], aA.y, b0.y);
            FMA2(acc2[1][2], aA.y, b1.x); FMA2(acc2[1][3], aA.y, b1.y);
            FMA2(acc2[1][4], aA.y, b2.x); FMA2(acc2[1][5], aA.y, b2.y);
            FMA2(acc2[1][6], aA.y, b3.x); FMA2(acc2[1][7], aA.y, b3.y);
            FMA2(acc2[2][0], aB.x, b0.x); FMA2(acc2[2][1], aB.x, b0.y);
            FMA2(acc2[2][2], aB.x, b1.x); FMA2(acc2[2][3], aB.x, b1.y);
            FMA2(acc2[2][4], aB.x, b2.x); FMA2(acc2[2][5], aB.x, b2.y);
            FMA2(acc2[2][6], aB.x, b3.x); FMA2(acc2[2][7], aB.x, b3.y);
            FMA2(acc2[3][0], aB.y, b0.x); FMA2(acc2[3][1], aB.y, b0.y);
            FMA2(acc2[3][2], aB.y, b1.x); FMA2(acc2[3][3], aB.y, b1.y);
            FMA2(acc2[3][4], aB.y, b2.x); FMA2(acc2[3][5], aB.y, b2.y);
            FMA2(acc2[3][6], aB.y, b3.x); FMA2(acc2[3][7], aB.y, b3.y);
        }

        if (pre) {
            int s = (t + 1) & 1;
            STAGE15(s, na0, na1, nvb);
            __syncthreads();
        }
    }

    // epilogue (row pairs: rows ty*8+2ip, +1; cols tx*8..tx*8+7)
#pragma unroll
    for (int ip = 0; ip < 4; ip++) {
        int row0 = bm + ty*8 + 2*ip;
        int col  = bn + tx*8;
        float4 c0a, c1a, c0b, c1b;
        UNPACK2(c0a.x, c1a.x, acc2[ip][0]);
        UNPACK2(c0a.y, c1a.y, acc2[ip][1]);
        UNPACK2(c0a.z, c1a.z, acc2[ip][2]);
        UNPACK2(c0a.w, c1a.w, acc2[ip][3]);
        UNPACK2(c0b.x, c1b.x, acc2[ip][4]);
        UNPACK2(c0b.y, c1b.y, acc2[ip][5]);
        UNPACK2(c0b.z, c1b.z, acc2[ip][6]);
        UNPACK2(c0b.w, c1b.w, acc2[ip][7]);
        float4 bva = *(const float4*)(bias + col);
        float4 bvb = *(const float4*)(bias + col + 4);
        c0a.x += bva.x; c0a.y += bva.y; c0a.z += bva.z; c0a.w += bva.w;
        c1a.x += bva.x; c1a.y += bva.y; c1a.z += bva.z; c1a.w += bva.w;
        c0b.x += bvb.x; c0b.y += bvb.y; c0b.z += bvb.z; c0b.w += bvb.w;
        c1b.x += bvb.x; c1b.y += bvb.y; c1b.z += bvb.z; c1b.w += bvb.w;
        if (mode) {
            float4 r0a = *(const float4*)(res + (size_t)row0 * N + col);
            float4 r0b = *(const float4*)(res + (size_t)row0 * N + col + 4);
            float4 r1a = *(const float4*)(res + (size_t)(row0+1) * N + col);
            float4 r1b = *(const float4*)(res + (size_t)(row0+1) * N + col + 4);
            c0a.x += r0a.x; c0a.y += r0a.y; c0a.z += r0a.z; c0a.w += r0a.w;
            c0b.x += r0b.x; c0b.y += r0b.y; c0b.z += r0b.z; c0b.w += r0b.w;
            c1a.x += r1a.x; c1a.y += r1a.y; c1a.z += r1a.z; c1a.w += r1a.w;
            c1b.x += r1b.x; c1b.y += r1b.y; c1b.z += r1b.z; c1b.w += r1b.w;
        }
        *(float4*)(C + (size_t)row0 * N + col)         = c0a;
        *(float4*)(C + (size_t)row0 * N + col + 4)     = c0b;
        *(float4*)(C + (size_t)(row0+1) * N + col)     = c1a;
        *(float4*)(C + (size_t)(row0+1) * N + col + 4) = c1b;
    }
}

// ---------------- RoPE + layout transform (Q pre-scaled) ----------------
__global__ void __launch_bounds__(256) rope_kernel()
{
    __shared__ float sq[64][65];
    __shared__ float sk[64][65];

    const int bh = blockIdx.y;
    const int b  = bh / NH;
    const int h  = bh % NH;
    const int s0 = blockIdx.x * 64;
    const int tid = threadIdx.x;
    const int d4 = (tid & 15) * 4;   // 0..60
    const int r0 = tid >> 4;         // 0..15

#pragma unroll
    for (int rep = 0; rep < 4; rep++) {
        int sl = r0 + rep * 16;
        int s  = s0 + sl;
        size_t base = ((size_t)(b * SS + s)) * N4H + h * DD;
        float4 q  = *(const float4*)(g_proj + base + 2*HH + d4);
        float4 k  = *(const float4*)(g_proj + base + 3*HH + d4);
        float4 v  = *(const float4*)(g_proj + base +   HH + d4);
        int dp = (d4 < 32) ? d4 + 32 : d4 - 32;
        float sgn = (d4 < 32) ? -1.f : 1.f;
        float4 qp = *(const float4*)(g_proj + base + 2*HH + dp);
        float4 kp = *(const float4*)(g_proj + base + 3*HH + dp);
        float4 cs = *(const float4*)(g_cos + s*DD + d4);
        float4 sn = *(const float4*)(g_sin + s*DD + d4);

        *(float4*)(g_V + ((size_t)bh * SS + s) * DD + d4) = v;

        sq[d4+0][sl] = q.x * cs.x + sgn * qp.x * sn.x;
        sq[d4+1][sl] = q.y * cs.y + sgn * qp.y * sn.y;
        sq[d4+2][sl] = q.z * cs.z + sgn * qp.z * sn.z;
        sq[d4+3][sl] = q.w * cs.w + sgn * qp.w * sn.w;

        sk[d4+0][sl] = k.x * cs.x + sgn * kp.x * sn.x;
        sk[d4+1][sl] = k.y * cs.y + sgn * kp.y * sn.y;
        sk[d4+2][sl] = k.z * cs.z + sgn * kp.z * sn.z;
        sk[d4+3][sl] = k.w * cs.w + sgn * kp.w * sn.w;
    }
    __syncthreads();

#pragma unroll
    for (int rep = 0; rep < 4; rep++) {
        int drow = r0 + rep * 16;
        int s4 = d4;
        float4 oq, ok;
        oq.x = sq[drow][s4+0] * Q_PRESCALE;
        oq.y = sq[drow][s4+1] * Q_PRESCALE;
        oq.z = sq[drow][s4+2] * Q_PRESCALE;
        oq.w = sq[drow][s4+3] * Q_PRESCALE;
        ok.x = sk[drow][s4+0]; ok.y = sk[drow][s4+1]; ok.z = sk[drow][s4+2]; ok.w = sk[drow][s4+3];
        *(float4*)(g_Qt + ((size_t)bh * DD + drow) * SS + s0 + s4) = oq;
        *(float4*)(g_Kt + ((size_t)bh * DD + drow) * SS + s0 + s4) = ok;
    }
}

// ---------------- fused causal sigmoid attention (r13, best measured) -------
#define ATTN_SMEM ((8192 + 2*4096 + 4096 + 8192) * 4)   /* 112KB */

__global__ void __launch_bounds__(256, 2) attn_kernel()
{
    extern __shared__ float smx[];
    float* Qs  = smx;                 // [64][128]  [d][q]
    float* Ks0 = smx + 8192;          // [64][64]   [d][k] buf 0
    float* Ks1 = smx + 12288;         // [64][64]   [d][k] buf 1
    float* Vs  = smx + 16384;         // [64][64]   [k][d]
    float* STs = smx + 20480;         // [64][128]  [k][q]  (swizzled)

    const int bh = blockIdx.y;
    const int qb = 15 - blockIdx.x;
    const int tid = threadIdx.x;
    const int tx = tid & 15;
    const int ty = tid >> 4;

#pragma unroll
    for (int i = 0; i < 8; i++) {
        int idx = tid + 256 * i;
        int d = idx >> 5;
        int c = (idx & 31) << 2;
        *(float4*)(Qs + d * 128 + c) =
            *(const float4*)(g_Qt + ((size_t)bh * DD + d) * SS + qb * 128 + c);
    }

#pragma unroll
    for (int i = 0; i < 4; i++) {
        int idx = tid + 256 * i;
        int d = idx >> 4;
        int c = (idx & 15) << 2;
        cp16(Ks0 + d * 64 + c,
             g_Kt + ((size_t)bh * DD + d) * SS + 0 * 64 + c);
    }
    CP_COMMIT();

    u64 o2[4][4];
#pragma unroll
    for (int i = 0; i < 4; i++)
#pragma unroll
        for (int d = 0; d < 4; d++) o2[i][d] = 0ull;

    const int ktmax = 2 * qb + 1;
    for (int kt = 0; kt <= ktmax; kt++) {
        float* Kcur = (kt & 1) ? Ks1 : Ks0;
        float* Knxt = (kt & 1) ? Ks0 : Ks1;

        CP_WAIT0();
        __syncthreads();

#pragma unroll
        for (int i = 0; i < 4; i++) {
            int idx = tid + 256 * i;
            int k = idx >> 4;
            int c = (idx & 15) << 2;
            cp16(Vs + k * 64 + c,
                 g_V + ((size_t)bh * SS + kt * 64 + k) * DD + c);
        }
        CP_COMMIT();

        if (kt < ktmax) {
#pragma unroll
            for (int i = 0; i < 4; i++) {
                int idx = tid + 256 * i;
                int d = idx >> 4;
                int c = (idx & 15) << 2;
                cp16(Knxt + d * 64 + c,
                     g_Kt + ((size_t)bh * DD + d) * SS + (kt + 1) * 64 + c);
            }
        }
        CP_COMMIT();

        u64 s2[4][4];
#pragma unroll
        for (int i = 0; i < 4; i++)
#pragma unroll
            for (int j = 0; j < 4; j++) s2[i][j] = 0ull;

#pragma unroll 4
        for (int kk = 0; kk < 64; kk++) {
            float4 a0 = *(float4*)(Qs + kk * 128 + ty * 8);
            float4 a1 = *(float4*)(Qs + kk * 128 + ty * 8 + 4);
            float4 b0 = *(float4*)(Kcur + kk * 64 + tx * 4);
            u64 ap[4];
            PACK2(ap[0], a0.x, a0.y); PACK2(ap[1], a0.z, a0.w);
            PACK2(ap[2], a1.x, a1.y); PACK2(ap[3], a1.z, a1.w);
            u64 bd[4];
            PACK2(bd[0], b0.x, b0.x); PACK2(bd[1], b0.y, b0.y);
            PACK2(bd[2], b0.z, b0.z); PACK2(bd[3], b0.w, b0.w);
#pragma unroll
            for (int i = 0; i < 4; i++)
#pragma unroll
                for (int j = 0; j < 4; j++)
                    FMA2(s2[i][j], ap[i], bd[j]);
        }

        const bool diagzone = (kt >= 2 * qb);
        const int koff = (kt - 2 * qb) * 64;
#pragma unroll
        for (int j = 0; j < 4; j++) {
            int krow = tx * 4 + j;
#pragma unroll
            for (int i = 0; i < 4; i++) {
                float sa, sb;
                UNPACK2(sa, sb, s2[i][j]);
                float pa = __fdividef(1.f, 1.f + ex2f(-sa));
                float pb = __fdividef(1.f, 1.f + ex2f(-sb));
                if (diagzone) {
                    int qa = ty * 8 + 2 * i;
                    if (koff + krow > qa)     pa = 0.f;
                    if (koff + krow > qa + 1) pb = 0.f;
                }
                int c4s = (ty * 2 + (i >> 1)) ^ tx;
                float2 pv; pv.x = pa; pv.y = pb;
                *(float2*)(STs + krow * 128 + c4s * 4 + (i & 1) * 2) = pv;
            }
        }
        CP_WAIT1G();
        __syncthreads();

#pragma unroll 4
        for (int t = 0; t < 64; t++) {
            int g = (t >> 2) & 15;
            float4 s0 = *(float4*)(STs + t * 128 + ((ty * 2)     ^ g) * 4);
            float4 s1 = *(float4*)(STs + t * 128 + ((ty * 2 + 1) ^ g) * 4);
            float4 vv = *(float4*)(Vs + t * 64 + tx * 4);
            u64 sp[4];
            PACK2(sp[0], s0.x, s0.y); PACK2(sp[1], s0.z, s0.w);
            PACK2(sp[2], s1.x, s1.y); PACK2(sp[3], s1.z, s1.w);
            u64 vd[4];
            PACK2(vd[0], vv.x, vv.x); PACK2(vd[1], vv.y, vv.y);
            PACK2(vd[2], vv.z, vv.z); PACK2(vd[3], vv.w, vv.w);
#pragma unroll
            for (int i = 0; i < 4; i++)
#pragma unroll
                for (int d = 0; d < 4; d++)
                    FMA2(o2[i][d], sp[i], vd[d]);
        }
    }

    const int b = bh / NH;
    const int h = bh % NH;
#pragma unroll
    for (int i = 0; i < 4; i++) {
        int q0 = qb * 128 + ty * 8 + 2 * i;
        float4 r0, r1;
        UNPACK2(r0.x, r1.x, o2[i][0]);
        UNPACK2(r0.y, r1.y, o2[i][1]);
        UNPACK2(r0.z, r1.z, o2[i][2]);
        UNPACK2(r0.w, r1.w, o2[i][3]);
        *(float4*)(g_attn + ((size_t)(b * SS + q0))     * HH + h * DD + tx * 4) = r0;
        *(float4*)(g_attn + ((size_t)(b * SS + q0 + 1)) * HH + h * DD + tx * 4) = r1;
    }
}

// ---------------- LayerNorm + SiLU gate (in-place into g_attn) --------------
__device__ __forceinline__ float block_reduce_sum(float v, float* red)
{
    int lane = threadIdx.x & 31;
    int wid  = threadIdx.x >> 5;
#pragma unroll
    for (int o = 16; o > 0; o >>= 1) v += __shfl_xor_sync(0xffffffffu, v, o);
    if (lane == 0) red[wid] = v;
    __syncthreads();
    float r = (lane < 8) ? red[lane] : 0.f;
    if (wid == 0) {
#pragma unroll
        for (int o = 4; o > 0; o >>= 1) r += __shfl_xor_sync(0xffffffffu, r, o);
        if (lane == 0) red[0] = r;
    }
    __syncthreads();
    float out = red[0];
    __syncthreads();
    return out;
}

__global__ void __launch_bounds__(256) ln_gate_kernel(
    const float* __restrict__ gamma, const float* __restrict__ beta)
{
    __shared__ float sm[HH];
    __shared__ float red[32];
    const int row = blockIdx.x;
    const int tid = threadIdx.x;

    float loc = 0.f;
#pragma unroll
    for (int k = 0; k < 3; k++) {
        int i = tid + k * 256;
        float v = g_attn[(size_t)row * HH + i];
        sm[i] = v;
        loc += v;
    }
    float mu = block_reduce_sum(loc, red) * (1.f / HH);

    float loc2 = 0.f;
#pragma unroll
    for (int k = 0; k < 3; k++) {
        int i = tid + k * 256;
        float d = sm[i] - mu;
        loc2 += d * d;
    }
    float var = block_reduce_sum(loc2, red) * (1.f / HH);
    float rstd = rsqrtf(var + 1e-8f);

#pragma unroll
    for (int k = 0; k < 3; k++) {
        int i = tid + k * 256;
        float ln = (sm[i] - mu) * rstd * gamma[i] + beta[i];
        float u = g_proj[(size_t)row * N4H + i];   // U = first quarter
        float silu = __fdividef(u, 1.f + __expf(-u));
        g_attn[(size_t)row * HH + i] = silu * ln;  // in-place
    }
}

// ---------------- launch ----------------
extern "C" void kernel_launch(void* const* d_in, const int* in_sizes, int n_in,
                              void* d_out, int out_size)
{
    const float* x      = (const float*)d_in[0];
    // d_in[1] = attn_mask (causal tril bool) — structure hardcoded
    const float* W_proj = (const float*)d_in[2];
    const float* b_proj = (const float*)d_in[3];
    const float* gamma  = (const float*)d_in[4];
    const float* beta   = (const float*)d_in[5];
    const float* W_out  = (const float*)d_in[6];
    const float* b_out  = (const float*)d_in[7];
    float* out = (float*)d_out;

    cudaFuncSetAttribute(attn_kernel,
        cudaFuncAttributeMaxDynamicSharedMemorySize, ATTN_SMEM);

    // 1. RoPE tables + weight duplication staging
    rope_table_kernel<<<SS, DD>>>();
    dup_b_kernel<<<(int)(((size_t)HH * (N4H/128) * 64 + 255) / 256), 256>>>(
        W_proj, N4H, 0);
    dup_b_kernel<<<(int)(((size_t)HH * (HH/128) * 64 + 255) / 256), 256>>>(
        W_out, HH, 1);

    // 2. proj = x @ W_proj + b_proj
    gemm_kernel<<<dim3(N4H/128, M_TOT/128), 256>>>(
        x, b_proj, nullptr, nullptr, N4H, 0);

    // 3. RoPE + transpose into attention layouts
    rope_kernel<<<dim3(SS/64, BB*NH), 256>>>();

    // 4. fused causal sigmoid attention
    attn_kernel<<<dim3(SS/128, BB*NH), 256, ATTN_SMEM>>>();

    // 5. LayerNorm + SiLU(U) gate (in-place into g_attn)
    ln_gate_kernel<<<M_TOT, 256>>>(gamma, beta);

    // 6. out = residual + gated @ W_out + b_out
    gemm_kernel<<<dim3(HH/128, M_TOT/128), 256>>>(
        nullptr, b_out, x, out, HH, 1);
}

// round 16
// speedup vs baseline: 1.1059x; 1.0166x over previous
#include <cuda_runtime.h>
#include <math.h>
#include <stdint.h>

#define BB 4
#define SS 2048
#define HH 768
#define NH 12
#define DD 64
#define M_TOT (BB*SS)      /* 8192 */
#define N4H (4*HH)         /* 3072 */

typedef unsigned long long u64;

// ---------------- scratch (static device globals; referenced ONLY in-kernel) -
__device__ float g_proj[(size_t)M_TOT * N4H];      // [8192][3072] : U|V|Q|K
__device__ float g_Qt[(size_t)BB*NH*DD*SS];        // [bh][d][s] (pre-scaled)
__device__ float g_Kt[(size_t)BB*NH*DD*SS];        // [bh][d][s]
__device__ float g_V [(size_t)BB*NH*SS*DD];        // [bh][s][d]
__device__ float g_attn[(size_t)M_TOT * HH];       // attn out; gated in-place
__device__ float g_cos[SS*DD];
__device__ float g_sin[SS*DD];

// ---------------- packed f32x2 helpers (Blackwell FFMA2) --------------------
#define PACK2(u, lo, hi) \
    asm("mov.b64 %0, {%1, %2};" : "=l"(u) : "f"(lo), "f"(hi))
#define UNPACK2(lo, hi, u) \
    asm("mov.b64 {%0, %1}, %2;" : "=f"(lo), "=f"(hi) : "l"(u))
#define FMA2(d, a, b) \
    asm("fma.rn.f32x2 %0, %1, %2, %0;" : "+l"(d) : "l"(a), "l"(b))

__device__ __forceinline__ float ex2f(float x) {
    float r; asm("ex2.approx.f32 %0, %1;" : "=f"(r) : "f"(x)); return r;
}

// cp.async helpers (16B)
__device__ __forceinline__ void cp16(void* dst_smem, const void* src) {
    uint32_t d = (uint32_t)__cvta_generic_to_shared(dst_smem);
    asm volatile("cp.async.cg.shared.global [%0], [%1], 16;\n" :: "r"(d), "l"(src));
}
#define CP_COMMIT()  asm volatile("cp.async.commit_group;\n" ::: "memory")
#define CP_WAIT0()   asm volatile("cp.async.wait_group 0;\n" ::: "memory")
#define CP_WAIT1G()  asm volatile("cp.async.wait_group 1;\n" ::: "memory")

// scale folded into Qt: 0.125 * log2(e)
#define Q_PRESCALE 0.18033688011112042f

// ---------------- RoPE tables ----------------
__global__ void rope_table_kernel() {
    int s = blockIdx.x;
    int d = threadIdx.x;          // 0..63
    int p = d & 31;
    double invd = pow(10000.0, -((double)(2 * p)) / 64.0);
    float theta = (float)s * (float)invd;     // fp32 quantized like reference
    float sn, cs;
    sincosf(theta, &sn, &cs);
    g_cos[s*DD + d] = cs;
    g_sin[s*DD + d] = sn;
}

// ---------------- fp32 tiled GEMM (r11, best measured) ----------------------
// mode 0: A = Aext (x), C = g_proj          (proj GEMM)
// mode 1: A = g_attn (gated), C = Cext, res added  (out GEMM)
__global__ void __launch_bounds__(256, 2) gemm_kernel(
    const float* __restrict__ Aext, const float* __restrict__ Bw,
    const float* __restrict__ bias, const float* __restrict__ res,
    float* __restrict__ Cext, int M, int N, int K, int mode)
{
    __shared__ float As[2][16][128];
    __shared__ float Bs[2][16][128];

    const float* A = mode ? g_attn : Aext;
    float* C       = mode ? Cext   : g_proj;

    const int bm = blockIdx.y * 128;
    const int bn = blockIdx.x * 128;
    const int tid = threadIdx.x;
    const int tx = tid & 15;          // col group
    const int ty = tid >> 4;          // row group

    const int ar = tid >> 2;          // 0..63
    const int ac = (tid & 3) << 2;    // 0,4,8,12
    const int br = tid >> 5;          // 0..7
    const int bc = (tid & 31) << 2;   // 0..124

    u64 acc2[4][8];                   // [row-pair ip][col j]
#pragma unroll
    for (int ip = 0; ip < 4; ip++)
#pragma unroll
        for (int j = 0; j < 8; j++) acc2[ip][j] = 0ull;

    // prologue: chunk 0 -> buf 0
    {
        float4 a0 = *(const float4*)(A + (size_t)(bm + ar)      * K + ac);
        float4 a1 = *(const float4*)(A + (size_t)(bm + ar + 64) * K + ac);
        float4 b0 = *(const float4*)(Bw + (size_t)(br)     * N + bn + bc);
        float4 b1 = *(const float4*)(Bw + (size_t)(br + 8) * N + bn + bc);
        As[0][ac+0][ar] = a0.x; As[0][ac+1][ar] = a0.y;
        As[0][ac+2][ar] = a0.z; As[0][ac+3][ar] = a0.w;
        As[0][ac+0][ar+64] = a1.x; As[0][ac+1][ar+64] = a1.y;
        As[0][ac+2][ar+64] = a1.z; As[0][ac+3][ar+64] = a1.w;
        *(float4*)&Bs[0][br][bc]   = b0;
        *(float4*)&Bs[0][br+8][bc] = b1;
    }
    __syncthreads();

    const int T = K / 16;
    for (int t = 0; t < T; t++) {
        float4 na0, na1, nb0, nb1;
        const bool pre = (t + 1 < T);
        if (pre) {
            int k0 = (t + 1) * 16;
            na0 = *(const float4*)(A + (size_t)(bm + ar)      * K + k0 + ac);
            na1 = *(const float4*)(A + (size_t)(bm + ar + 64) * K + k0 + ac);
            nb0 = *(const float4*)(Bw + (size_t)(k0 + br)     * N + bn + bc);
            nb1 = *(const float4*)(Bw + (size_t)(k0 + br + 8) * N + bn + bc);
        }

        const float (*AS)[128] = As[t & 1];
        const float (*BS)[128] = Bs[t & 1];
#pragma unroll
        for (int kk = 0; kk < 16; kk++) {
            ulonglong2 aA = *(const ulonglong2*)&AS[kk][ty*8];
            ulonglong2 aB = *(const ulonglong2*)&AS[kk][ty*8 + 4];
            float4 bv0 = *(const float4*)&BS[kk][tx*8];
            float4 bv1 = *(const float4*)&BS[kk][tx*8 + 4];
            u64 bd0, bd1, bd2, bd3, bd4, bd5, bd6, bd7;
            PACK2(bd0, bv0.x, bv0.x); PACK2(bd1, bv0.y, bv0.y);
            PACK2(bd2, bv0.z, bv0.z); PACK2(bd3, bv0.w, bv0.w);
            PACK2(bd4, bv1.x, bv1.x); PACK2(bd5, bv1.y, bv1.y);
            PACK2(bd6, bv1.z, bv1.z); PACK2(bd7, bv1.w, bv1.w);
            FMA2(acc2[0][0], aA.x, bd0); FMA2(acc2[0][1], aA.x, bd1);
            FMA2(acc2[0][2], aA.x, bd2); FMA2(acc2[0][3], aA.x, bd3);
            FMA2(acc2[0][4], aA.x, bd4); FMA2(acc2[0][5], aA.x, bd5);
            FMA2(acc2[0][6], aA.x, bd6); FMA2(acc2[0][7], aA.x, bd7);
            FMA2(acc2[1][0], aA.y, bd0); FMA2(acc2[1][1], aA.y, bd1);
            FMA2(acc2[1][2], aA.y, bd2); FMA2(acc2[1][3], aA.y, bd3);
            FMA2(acc2[1][4], aA.y, bd4); FMA2(acc2[1][5], aA.y, bd5);
            FMA2(acc2[1][6], aA.y, bd6); FMA2(acc2[1][7], aA.y, bd7);
            FMA2(acc2[2][0], aB.x, bd0); FMA2(acc2[2][1], aB.x, bd1);
            FMA2(acc2[2][2], aB.x, bd2); FMA2(acc2[2][3], aB.x, bd3);
            FMA2(acc2[2][4], aB.x, bd4); FMA2(acc2[2][5], aB.x, bd5);
            FMA2(acc2[2][6], aB.x, bd6); FMA2(acc2[2][7], aB.x, bd7);
            FMA2(acc2[3][0], aB.y, bd0); FMA2(acc2[3][1], aB.y, bd1);
            FMA2(acc2[3][2], aB.y, bd2); FMA2(acc2[3][3], aB.y, bd3);
            FMA2(acc2[3][4], aB.y, bd4); FMA2(acc2[3][5], aB.y, bd5);
            FMA2(acc2[3][6], aB.y, bd6); FMA2(acc2[3][7], aB.y, bd7);
        }

        if (pre) {
            int s = (t + 1) & 1;
            As[s][ac+0][ar] = na0.x; As[s][ac+1][ar] = na0.y;
            As[s][ac+2][ar] = na0.z; As[s][ac+3][ar] = na0.w;
            As[s][ac+0][ar+64] = na1.x; As[s][ac+1][ar+64] = na1.y;
            As[s][ac+2][ar+64] = na1.z; As[s][ac+3][ar+64] = na1.w;
            *(float4*)&Bs[s][br][bc]   = nb0;
            *(float4*)&Bs[s][br+8][bc] = nb1;
            __syncthreads();
        }
    }

    // epilogue
#pragma unroll
    for (int ip = 0; ip < 4; ip++) {
        int row0 = bm + ty*8 + 2*ip;
        int col  = bn + tx*8;
        float4 c0a, c1a, c0b, c1b;
        UNPACK2(c0a.x, c1a.x, acc2[ip][0]);
        UNPACK2(c0a.y, c1a.y, acc2[ip][1]);
        UNPACK2(c0a.z, c1a.z, acc2[ip][2]);
        UNPACK2(c0a.w, c1a.w, acc2[ip][3]);
        UNPACK2(c0b.x, c1b.x, acc2[ip][4]);
        UNPACK2(c0b.y, c1b.y, acc2[ip][5]);
        UNPACK2(c0b.z, c1b.z, acc2[ip][6]);
        UNPACK2(c0b.w, c1b.w, acc2[ip][7]);
        float4 bva = *(const float4*)(bias + col);
        float4 bvb = *(const float4*)(bias + col + 4);
        c0a.x += bva.x; c0a.y += bva.y; c0a.z += bva.z; c0a.w += bva.w;
        c1a.x += bva.x; c1a.y += bva.y; c1a.z += bva.z; c1a.w += bva.w;
        c0b.x += bvb.x; c0b.y += bvb.y; c0b.z += bvb.z; c0b.w += bvb.w;
        c1b.x += bvb.x; c1b.y += bvb.y; c1b.z += bvb.z; c1b.w += bvb.w;
        if (mode) {
            float4 r0a = *(const float4*)(res + (size_t)row0 * N + col);
            float4 r0b = *(const float4*)(res + (size_t)row0 * N + col + 4);
            float4 r1a = *(const float4*)(res + (size_t)(row0+1) * N + col);
            float4 r1b = *(const float4*)(res + (size_t)(row0+1) * N + col + 4);
            c0a.x += r0a.x; c0a.y += r0a.y; c0a.z += r0a.z; c0a.w += r0a.w;
            c0b.x += r0b.x; c0b.y += r0b.y; c0b.z += r0b.z; c0b.w += r0b.w;
            c1a.x += r1a.x; c1a.y += r1a.y; c1a.z += r1a.z; c1a.w += r1a.w;
            c1b.x += r1b.x; c1b.y += r1b.y; c1b.z += r1b.z; c1b.w += r1b.w;
        }
        *(float4*)(C + (size_t)row0 * N + col)         = c0a;
        *(float4*)(C + (size_t)row0 * N + col + 4)     = c0b;
        *(float4*)(C + (size_t)(row0+1) * N + col)     = c1a;
        *(float4*)(C + (size_t)(row0+1) * N + col + 4) = c1b;
    }
}

// ---------------- RoPE + layout transform (Q pre-scaled) ----------------
__global__ void __launch_bounds__(256) rope_kernel()
{
    __shared__ float sq[64][65];
    __shared__ float sk[64][65];

    const int bh = blockIdx.y;
    const int b  = bh / NH;
    const int h  = bh % NH;
    const int s0 = blockIdx.x * 64;
    const int tid = threadIdx.x;
    const int d4 = (tid & 15) * 4;   // 0..60
    const int r0 = tid >> 4;         // 0..15

#pragma unroll
    for (int rep = 0; rep < 4; rep++) {
        int sl = r0 + rep * 16;
        int s  = s0 + sl;
        size_t base = ((size_t)(b * SS + s)) * N4H + h * DD;
        float4 q  = *(const float4*)(g_proj + base + 2*HH + d4);
        float4 k  = *(const float4*)(g_proj + base + 3*HH + d4);
        float4 v  = *(const float4*)(g_proj + base +   HH + d4);
        int dp = (d4 < 32) ? d4 + 32 : d4 - 32;
        float sgn = (d4 < 32) ? -1.f : 1.f;
        float4 qp = *(const float4*)(g_proj + base + 2*HH + dp);
        float4 kp = *(const float4*)(g_proj + base + 3*HH + dp);
        float4 cs = *(const float4*)(g_cos + s*DD + d4);
        float4 sn = *(const float4*)(g_sin + s*DD + d4);

        *(float4*)(g_V + ((size_t)bh * SS + s) * DD + d4) = v;

        sq[d4+0][sl] = q.x * cs.x + sgn * qp.x * sn.x;
        sq[d4+1][sl] = q.y * cs.y + sgn * qp.y * sn.y;
        sq[d4+2][sl] = q.z * cs.z + sgn * qp.z * sn.z;
        sq[d4+3][sl] = q.w * cs.w + sgn * qp.w * sn.w;

        sk[d4+0][sl] = k.x * cs.x + sgn * kp.x * sn.x;
        sk[d4+1][sl] = k.y * cs.y + sgn * kp.y * sn.y;
        sk[d4+2][sl] = k.z * cs.z + sgn * kp.z * sn.z;
        sk[d4+3][sl] = k.w * cs.w + sgn * kp.w * sn.w;
    }
    __syncthreads();

#pragma unroll
    for (int rep = 0; rep < 4; rep++) {
        int drow = r0 + rep * 16;
        int s4 = d4;
        float4 oq, ok;
        oq.x = sq[drow][s4+0] * Q_PRESCALE;
        oq.y = sq[drow][s4+1] * Q_PRESCALE;
        oq.z = sq[drow][s4+2] * Q_PRESCALE;
        oq.w = sq[drow][s4+3] * Q_PRESCALE;
        ok.x = sk[drow][s4+0]; ok.y = sk[drow][s4+1]; ok.z = sk[drow][s4+2]; ok.w = sk[drow][s4+3];
        *(float4*)(g_Qt + ((size_t)bh * DD + drow) * SS + s0 + s4) = oq;
        *(float4*)(g_Kt + ((size_t)bh * DD + drow) * SS + s0 + s4) = ok;
    }
}

// ---------------- fused causal sigmoid attention (r13, best measured) -------
#define ATTN_SMEM ((8192 + 2*4096 + 4096 + 8192) * 4)   /* 112KB */

__global__ void __launch_bounds__(256, 2) attn_kernel()
{
    extern __shared__ float smx[];
    float* Qs  = smx;                 // [64][128]  [d][q]
    float* Ks0 = smx + 8192;          // [64][64]   [d][k] buf 0
    float* Ks1 = smx + 12288;         // [64][64]   [d][k] buf 1
    float* Vs  = smx + 16384;         // [64][64]   [k][d]
    float* STs = smx + 20480;         // [64][128]  [k][q]  (swizzled)

    const int bh = blockIdx.y;
    const int qb = 15 - blockIdx.x;
    const int tid = threadIdx.x;
    const int tx = tid & 15;
    const int ty = tid >> 4;

#pragma unroll
    for (int i = 0; i < 8; i++) {
        int idx = tid + 256 * i;
        int d = idx >> 5;
        int c = (idx & 31) << 2;
        *(float4*)(Qs + d * 128 + c) =
            *(const float4*)(g_Qt + ((size_t)bh * DD + d) * SS + qb * 128 + c);
    }

#pragma unroll
    for (int i = 0; i < 4; i++) {
        int idx = tid + 256 * i;
        int d = idx >> 4;
        int c = (idx & 15) << 2;
        cp16(Ks0 + d * 64 + c,
             g_Kt + ((size_t)bh * DD + d) * SS + 0 * 64 + c);
    }
    CP_COMMIT();

    u64 o2[4][4];
#pragma unroll
    for (int i = 0; i < 4; i++)
#pragma unroll
        for (int d = 0; d < 4; d++) o2[i][d] = 0ull;

    const int ktmax = 2 * qb + 1;
    for (int kt = 0; kt <= ktmax; kt++) {
        float* Kcur = (kt & 1) ? Ks1 : Ks0;
        float* Knxt = (kt & 1) ? Ks0 : Ks1;

        CP_WAIT0();
        __syncthreads();

#pragma unroll
        for (int i = 0; i < 4; i++) {
            int idx = tid + 256 * i;
            int k = idx >> 4;
            int c = (idx & 15) << 2;
            cp16(Vs + k * 64 + c,
                 g_V + ((size_t)bh * SS + kt * 64 + k) * DD + c);
        }
        CP_COMMIT();

        if (kt < ktmax) {
#pragma unroll
            for (int i = 0; i < 4; i++) {
                int idx = tid + 256 * i;
                int d = idx >> 4;
                int c = (idx & 15) << 2;
                cp16(Knxt + d * 64 + c,
                     g_Kt + ((size_t)bh * DD + d) * SS + (kt + 1) * 64 + c);
            }
        }
        CP_COMMIT();

        u64 s2[4][4];
#pragma unroll
        for (int i = 0; i < 4; i++)
#pragma unroll
            for (int j = 0; j < 4; j++) s2[i][j] = 0ull;

#pragma unroll 4
        for (int kk = 0; kk < 64; kk++) {
            float4 a0 = *(float4*)(Qs + kk * 128 + ty * 8);
            float4 a1 = *(float4*)(Qs + kk * 128 + ty * 8 + 4);
            float4 b0 = *(float4*)(Kcur + kk * 64 + tx * 4);
            u64 ap[4];
            PACK2(ap[0], a0.x, a0.y); PACK2(ap[1], a0.z, a0.w);
            PACK2(ap[2], a1.x, a1.y); PACK2(ap[3], a1.z, a1.w);
            u64 bd[4];
            PACK2(bd[0], b0.x, b0.x); PACK2(bd[1], b0.y, b0.y);
            PACK2(bd[2], b0.z, b0.z); PACK2(bd[3], b0.w, b0.w);
#pragma unroll
            for (int i = 0; i < 4; i++)
#pragma unroll
                for (int j = 0; j < 4; j++)
                    FMA2(s2[i][j], ap[i], bd[j]);
        }

        const bool diagzone = (kt >= 2 * qb);
        const int koff = (kt - 2 * qb) * 64;
#pragma unroll
        for (int j = 0; j < 4; j++) {
            int krow = tx * 4 + j;
#pragma unroll
            for (int i = 0; i < 4; i++) {
                float sa, sb;
                UNPACK2(sa, sb, s2[i][j]);
                float pa = __fdividef(1.f, 1.f + ex2f(-sa));
                float pb = __fdividef(1.f, 1.f + ex2f(-sb));
                if (diagzone) {
                    int qa = ty * 8 + 2 * i;
                    if (koff + krow > qa)     pa = 0.f;
                    if (koff + krow > qa + 1) pb = 0.f;
                }
                int c4s = (ty * 2 + (i >> 1)) ^ tx;
                float2 pv; pv.x = pa; pv.y = pb;
                *(float2*)(STs + krow * 128 + c4s * 4 + (i & 1) * 2) = pv;
            }
        }
        CP_WAIT1G();
        __syncthreads();

#pragma unroll 4
        for (int t = 0; t < 64; t++) {
            int g = (t >> 2) & 15;
            float4 s0 = *(float4*)(STs + t * 128 + ((ty * 2)     ^ g) * 4);
            float4 s1 = *(float4*)(STs + t * 128 + ((ty * 2 + 1) ^ g) * 4);
            float4 vv = *(float4*)(Vs + t * 64 + tx * 4);
            u64 sp[4];
            PACK2(sp[0], s0.x, s0.y); PACK2(sp[1], s0.z, s0.w);
            PACK2(sp[2], s1.x, s1.y); PACK2(sp[3], s1.z, s1.w);
            u64 vd[4];
            PACK2(vd[0], vv.x, vv.x); PACK2(vd[1], vv.y, vv.y);
            PACK2(vd[2], vv.z, vv.z); PACK2(vd[3], vv.w, vv.w);
#pragma unroll
            for (int i = 0; i < 4; i++)
#pragma unroll
                for (int d = 0; d < 4; d++)
                    FMA2(o2[i][d], sp[i], vd[d]);
        }
    }

    const int b = bh / NH;
    const int h = bh % NH;
#pragma unroll
    for (int i = 0; i < 4; i++) {
        int q0 = qb * 128 + ty * 8 + 2 * i;
        float4 r0, r1;
        UNPACK2(r0.x, r1.x, o2[i][0]);
        UNPACK2(r0.y, r1.y, o2[i][1]);
        UNPACK2(r0.z, r1.z, o2[i][2]);
        UNPACK2(r0.w, r1.w, o2[i][3]);
        *(float4*)(g_attn + ((size_t)(b * SS + q0))     * HH + h * DD + tx * 4) = r0;
        *(float4*)(g_attn + ((size_t)(b * SS + q0 + 1)) * HH + h * DD + tx * 4) = r1;
    }
}

// ---------------- LayerNorm + SiLU gate (in-place into g_attn) --------------
__device__ __forceinline__ float block_reduce_sum(float v, float* red)
{
    int lane = threadIdx.x & 31;
    int wid  = threadIdx.x >> 5;
#pragma unroll
    for (int o = 16; o > 0; o >>= 1) v += __shfl_xor_sync(0xffffffffu, v, o);
    if (lane == 0) red[wid] = v;
    __syncthreads();
    float r = (lane < 8) ? red[lane] : 0.f;
    if (wid == 0) {
#pragma unroll
        for (int o = 4; o > 0; o >>= 1) r += __shfl_xor_sync(0xffffffffu, r, o);
        if (lane == 0) red[0] = r;
    }
    __syncthreads();
    float out = red[0];
    __syncthreads();
    return out;
}

__global__ void __launch_bounds__(256) ln_gate_kernel(
    const float* __restrict__ gamma, const float* __restrict__ beta)
{
    __shared__ float sm[HH];
    __shared__ float red[32];
    const int row = blockIdx.x;
    const int tid = threadIdx.x;

    float loc = 0.f;
#pragma unroll
    for (int k = 0; k < 3; k++) {
        int i = tid + k * 256;
        float v = g_attn[(size_t)row * HH + i];
        sm[i] = v;
        loc += v;
    }
    float mu = block_reduce_sum(loc, red) * (1.f / HH);

    float loc2 = 0.f;
#pragma unroll
    for (int k = 0; k < 3; k++) {
        int i = tid + k * 256;
        float d = sm[i] - mu;
        loc2 += d * d;
    }
    float var = block_reduce_sum(loc2, red) * (1.f / HH);
    float rstd = rsqrtf(var + 1e-8f);

#pragma unroll
    for (int k = 0; k < 3; k++) {
        int i = tid + k * 256;
        float ln = (sm[i] - mu) * rstd * gamma[i] + beta[i];
        float u = g_proj[(size_t)row * N4H + i];   // U = first quarter
        float silu = __fdividef(u, 1.f + __expf(-u));
        g_attn[(size_t)row * HH + i] = silu * ln;  // in-place
    }
}

// ---------------- launch ----------------
extern "C" void kernel_launch(void* const* d_in, const int* in_sizes, int n_in,
                              void* d_out, int out_size)
{
    const float* x      = (const float*)d_in[0];
    // d_in[1] = attn_mask (causal tril bool) — structure hardcoded
    const float* W_proj = (const float*)d_in[2];
    const float* b_proj = (const float*)d_in[3];
    const float* gamma  = (const float*)d_in[4];
    const float* beta   = (const float*)d_in[5];
    const float* W_out  = (const float*)d_in[6];
    const float* b_out  = (const float*)d_in[7];
    float* out = (float*)d_out;

    cudaFuncSetAttribute(attn_kernel,
        cudaFuncAttributeMaxDynamicSharedMemorySize, ATTN_SMEM);

    // 1. RoPE tables
    rope_table_kernel<<<SS, DD>>>();

    // 2. proj = x @ W_proj + b_proj
    gemm_kernel<<<dim3(N4H/128, M_TOT/128), 256>>>(
        x, W_proj, b_proj, nullptr, nullptr, M_TOT, N4H, HH, 0);

    // 3. RoPE + transpose into attention layouts
    rope_kernel<<<dim3(SS/64, BB*NH), 256>>>();

    // 4. fused causal sigmoid attention
    attn_kernel<<<dim3(SS/128, BB*NH), 256, ATTN_SMEM>>>();

    // 5. LayerNorm + SiLU(U) gate (in-place into g_attn)
    ln_gate_kernel<<<M_TOT, 256>>>(gamma, beta);

    // 6. out = residual + gated @ W_out + b_out
    gemm_kernel<<<dim3(HH/128, M_TOT/128), 256>>>(
        nullptr, W_out, b_out, x, out, M_TOT, HH, HH, 1);
}

// round 17
// speedup vs baseline: 1.1764x; 1.0637x over previous
#include <cuda_runtime.h>
#include <math.h>
#include <stdint.h>

#define BB 4
#define SS 2048
#define HH 768
#define NH 12
#define DD 64
#define M_TOT (BB*SS)      /* 8192 */
#define N4H (4*HH)         /* 3072 */

typedef unsigned long long u64;

// ---------------- scratch (static device globals; referenced ONLY in-kernel) -
__device__ float g_proj[(size_t)M_TOT * N4H];      // [8192][3072] : U|V|Q|K
__device__ float g_AT[(size_t)HH * M_TOT];         // A^T: xT, later gatedT
__device__ float g_Qt[(size_t)BB*NH*DD*SS];        // [bh][d][s] (pre-scaled)
__device__ float g_Kt[(size_t)BB*NH*DD*SS];        // [bh][d][s]
__device__ float g_V [(size_t)BB*NH*SS*DD];        // [bh][s][d]
__device__ float g_attn[(size_t)M_TOT * HH];       // attn out
__device__ float g_cos[SS*DD];
__device__ float g_sin[SS*DD];

// ---------------- packed f32x2 helpers (Blackwell FFMA2) --------------------
#define PACK2(u, lo, hi) \
    asm("mov.b64 %0, {%1, %2};" : "=l"(u) : "f"(lo), "f"(hi))
#define UNPACK2(lo, hi, u) \
    asm("mov.b64 {%0, %1}, %2;" : "=f"(lo), "=f"(hi) : "l"(u))
#define FMA2(d, a, b) \
    asm("fma.rn.f32x2 %0, %1, %2, %0;" : "+l"(d) : "l"(a), "l"(b))

__device__ __forceinline__ float ex2f(float x) {
    float r; asm("ex2.approx.f32 %0, %1;" : "=f"(r) : "f"(x)); return r;
}

// cp.async helpers (16B)
__device__ __forceinline__ void cp16(void* dst_smem, const void* src) {
    uint32_t d = (uint32_t)__cvta_generic_to_shared(dst_smem);
    asm volatile("cp.async.cg.shared.global [%0], [%1], 16;\n" :: "r"(d), "l"(src));
}
#define CP_COMMIT()  asm volatile("cp.async.commit_group;\n" ::: "memory")
#define CP_WAIT0()   asm volatile("cp.async.wait_group 0;\n" ::: "memory")
#define CP_WAIT1G()  asm volatile("cp.async.wait_group 1;\n" ::: "memory")
#define CP_WAIT2G()  asm volatile("cp.async.wait_group 2;\n" ::: "memory")

// scale folded into Qt: 0.125 * log2(e)
#define Q_PRESCALE 0.18033688011112042f

// ---------------- RoPE tables ----------------
__global__ void rope_table_kernel() {
    int s = blockIdx.x;
    int d = threadIdx.x;          // 0..63
    int p = d & 31;
    double invd = pow(10000.0, -((double)(2 * p)) / 64.0);
    float theta = (float)s * (float)invd;     // fp32 quantized like reference
    float sn, cs;
    sincosf(theta, &sn, &cs);
    g_cos[s*DD + d] = cs;
    g_sin[s*DD + d] = sn;
}

// ---------------- x -> g_AT (transpose, coalesced both sides) ---------------
__global__ void transpose_x_kernel(const float* __restrict__ x)
{
    __shared__ float t[32][33];
    int m0 = blockIdx.x * 32, k0 = blockIdx.y * 32;
    for (int i = threadIdx.y; i < 32; i += 8)
        t[i][threadIdx.x] = x[(size_t)(m0 + i) * HH + k0 + threadIdx.x];
    __syncthreads();
    for (int i = threadIdx.y; i < 32; i += 8)
        g_AT[(size_t)(k0 + i) * M_TOT + m0 + threadIdx.x] = t[threadIdx.x][i];
}

// ---------------- fp32 tiled GEMM: cp.async 3-stage, FMA2 inner -------------
// A = g_AT (K-major), B = Bw (K-major). mode 0: C=g_proj; mode 1: C=Cext(+res)
__global__ void __launch_bounds__(256, 2) gemm_kernel(
    const float* __restrict__ Bw,
    const float* __restrict__ bias, const float* __restrict__ res,
    float* __restrict__ Cext, int N, int mode)
{
    __shared__ float As[3][16][128];
    __shared__ float Bs[3][16][128];

    float* C = mode ? Cext : g_proj;

    const int bm = blockIdx.y * 128;
    const int bn = blockIdx.x * 128;
    const int tid = threadIdx.x;
    const int tx = tid & 15;          // col group
    const int ty = tid >> 4;          // row group

    u64 acc2[4][8];                   // [row-pair ip][col j]
#pragma unroll
    for (int ip = 0; ip < 4; ip++)
#pragma unroll
        for (int j = 0; j < 8; j++) acc2[ip][j] = 0ull;

#define GCOPY(c, s) do {                                                        \
    _Pragma("unroll")                                                           \
    for (int i = 0; i < 2; i++) {                                               \
        int f4 = tid + 256 * i;                                                 \
        int kk = f4 >> 5;                                                       \
        int c4 = (f4 & 31) << 2;                                                \
        cp16(&As[s][kk][c4], g_AT + (size_t)((c)*16 + kk) * M_TOT + bm + c4);   \
        cp16(&Bs[s][kk][c4], Bw  + (size_t)((c)*16 + kk) * N    + bn + c4);     \
    }                                                                           \
    CP_COMMIT();                                                                \
} while (0)

    GCOPY(0, 0);
    GCOPY(1, 1);

    const int T = HH / 16;  // 24
    for (int t = 0; t < T; t++) {
        __syncthreads();              // prev compute on slot (t+2)%3 done
        if (t + 2 < T) GCOPY(t + 2, (t + 2) % 3);
        else CP_COMMIT();             // empty group keeps accounting
        CP_WAIT2G();                  // group t arrived (2 phases ago)
        __syncthreads();              // visible to all warps

        const float (*AS)[128] = As[t % 3];
        const float (*BS)[128] = Bs[t % 3];
#pragma unroll
        for (int kk = 0; kk < 16; kk++) {
            ulonglong2 aA = *(const ulonglong2*)&AS[kk][ty*8];
            ulonglong2 aB = *(const ulonglong2*)&AS[kk][ty*8 + 4];
            float4 bv0 = *(const float4*)&BS[kk][tx*8];
            float4 bv1 = *(const float4*)&BS[kk][tx*8 + 4];
            u64 bd0, bd1, bd2, bd3, bd4, bd5, bd6, bd7;
            PACK2(bd0, bv0.x, bv0.x); PACK2(bd1, bv0.y, bv0.y);
            PACK2(bd2, bv0.z, bv0.z); PACK2(bd3, bv0.w, bv0.w);
            PACK2(bd4, bv1.x, bv1.x); PACK2(bd5, bv1.y, bv1.y);
            PACK2(bd6, bv1.z, bv1.z); PACK2(bd7, bv1.w, bv1.w);
            FMA2(acc2[0][0], aA.x, bd0); FMA2(acc2[0][1], aA.x, bd1);
            FMA2(acc2[0][2], aA.x, bd2); FMA2(acc2[0][3], aA.x, bd3);
            FMA2(acc2[0][4], aA.x, bd4); FMA2(acc2[0][5], aA.x, bd5);
            FMA2(acc2[0][6], aA.x, bd6); FMA2(acc2[0][7], aA.x, bd7);
            FMA2(acc2[1][0], aA.y, bd0); FMA2(acc2[1][1], aA.y, bd1);
            FMA2(acc2[1][2], aA.y, bd2); FMA2(acc2[1][3], aA.y, bd3);
            FMA2(acc2[1][4], aA.y, bd4); FMA2(acc2[1][5], aA.y, bd5);
            FMA2(acc2[1][6], aA.y, bd6); FMA2(acc2[1][7], aA.y, bd7);
            FMA2(acc2[2][0], aB.x, bd0); FMA2(acc2[2][1], aB.x, bd1);
            FMA2(acc2[2][2], aB.x, bd2); FMA2(acc2[2][3], aB.x, bd3);
            FMA2(acc2[2][4], aB.x, bd4); FMA2(acc2[2][5], aB.x, bd5);
            FMA2(acc2[2][6], aB.x, bd6); FMA2(acc2[2][7], aB.x, bd7);
            FMA2(acc2[3][0], aB.y, bd0); FMA2(acc2[3][1], aB.y, bd1);
            FMA2(acc2[3][2], aB.y, bd2); FMA2(acc2[3][3], aB.y, bd3);
            FMA2(acc2[3][4], aB.y, bd4); FMA2(acc2[3][5], aB.y, bd5);
            FMA2(acc2[3][6], aB.y, bd6); FMA2(acc2[3][7], aB.y, bd7);
        }
    }

    // epilogue
#pragma unroll
    for (int ip = 0; ip < 4; ip++) {
        int row0 = bm + ty*8 + 2*ip;
        int col  = bn + tx*8;
        float4 c0a, c1a, c0b, c1b;
        UNPACK2(c0a.x, c1a.x, acc2[ip][0]);
        UNPACK2(c0a.y, c1a.y, acc2[ip][1]);
        UNPACK2(c0a.z, c1a.z, acc2[ip][2]);
        UNPACK2(c0a.w, c1a.w, acc2[ip][3]);
        UNPACK2(c0b.x, c1b.x, acc2[ip][4]);
        UNPACK2(c0b.y, c1b.y, acc2[ip][5]);
        UNPACK2(c0b.z, c1b.z, acc2[ip][6]);
        UNPACK2(c0b.w, c1b.w, acc2[ip][7]);
        float4 bva = *(const float4*)(bias + col);
        float4 bvb = *(const float4*)(bias + col + 4);
        c0a.x += bva.x; c0a.y += bva.y; c0a.z += bva.z; c0a.w += bva.w;
        c1a.x += bva.x; c1a.y += bva.y; c1a.z += bva.z; c1a.w += bva.w;
        c0b.x += bvb.x; c0b.y += bvb.y; c0b.z += bvb.z; c0b.w += bvb.w;
        c1b.x += bvb.x; c1b.y += bvb.y; c1b.z += bvb.z; c1b.w += bvb.w;
        if (mode) {
            float4 r0a = *(const float4*)(res + (size_t)row0 * N + col);
            float4 r0b = *(const float4*)(res + (size_t)row0 * N + col + 4);
            float4 r1a = *(const float4*)(res + (size_t)(row0+1) * N + col);
            float4 r1b = *(const float4*)(res + (size_t)(row0+1) * N + col + 4);
            c0a.x += r0a.x; c0a.y += r0a.y; c0a.z += r0a.z; c0a.w += r0a.w;
            c0b.x += r0b.x; c0b.y += r0b.y; c0b.z += r0b.z; c0b.w += r0b.w;
            c1a.x += r1a.x; c1a.y += r1a.y; c1a.z += r1a.z; c1a.w += r1a.w;
            c1b.x += r1b.x; c1b.y += r1b.y; c1b.z += r1b.z; c1b.w += r1b.w;
        }
        *(float4*)(C + (size_t)row0 * N + col)         = c0a;
        *(float4*)(C + (size_t)row0 * N + col + 4)     = c0b;
        *(float4*)(C + (size_t)(row0+1) * N + col)     = c1a;
        *(float4*)(C + (size_t)(row0+1) * N + col + 4) = c1b;
    }
}

// ---------------- RoPE + layout transform (Q pre-scaled) ----------------
__global__ void __launch_bounds__(256) rope_kernel()
{
    __shared__ float sq[64][65];
    __shared__ float sk[64][65];

    const int bh = blockIdx.y;
    const int b  = bh / NH;
    const int h  = bh % NH;
    const int s0 = blockIdx.x * 64;
    const int tid = threadIdx.x;
    const int d4 = (tid & 15) * 4;   // 0..60
    const int r0 = tid >> 4;         // 0..15

#pragma unroll
    for (int rep = 0; rep < 4; rep++) {
        int sl = r0 + rep * 16;
        int s  = s0 + sl;
        size_t base = ((size_t)(b * SS + s)) * N4H + h * DD;
        float4 q  = *(const float4*)(g_proj + base + 2*HH + d4);
        float4 k  = *(const float4*)(g_proj + base + 3*HH + d4);
        float4 v  = *(const float4*)(g_proj + base +   HH + d4);
        int dp = (d4 < 32) ? d4 + 32 : d4 - 32;
        float sgn = (d4 < 32) ? -1.f : 1.f;
        float4 qp = *(const float4*)(g_proj + base + 2*HH + dp);
        float4 kp = *(const float4*)(g_proj + base + 3*HH + dp);
        float4 cs = *(const float4*)(g_cos + s*DD + d4);
        float4 sn = *(const float4*)(g_sin + s*DD + d4);

        *(float4*)(g_V + ((size_t)bh * SS + s) * DD + d4) = v;

        sq[d4+0][sl] = q.x * cs.x + sgn * qp.x * sn.x;
        sq[d4+1][sl] = q.y * cs.y + sgn * qp.y * sn.y;
        sq[d4+2][sl] = q.z * cs.z + sgn * qp.z * sn.z;
        sq[d4+3][sl] = q.w * cs.w + sgn * qp.w * sn.w;

        sk[d4+0][sl] = k.x * cs.x + sgn * kp.x * sn.x;
        sk[d4+1][sl] = k.y * cs.y + sgn * kp.y * sn.y;
        sk[d4+2][sl] = k.z * cs.z + sgn * kp.z * sn.z;
        sk[d4+3][sl] = k.w * cs.w + sgn * kp.w * sn.w;
    }
    __syncthreads();

#pragma unroll
    for (int rep = 0; rep < 4; rep++) {
        int drow = r0 + rep * 16;
        int s4 = d4;
        float4 oq, ok;
        oq.x = sq[drow][s4+0] * Q_PRESCALE;
        oq.y = sq[drow][s4+1] * Q_PRESCALE;
        oq.z = sq[drow][s4+2] * Q_PRESCALE;
        oq.w = sq[drow][s4+3] * Q_PRESCALE;
        ok.x = sk[drow][s4+0]; ok.y = sk[drow][s4+1]; ok.z = sk[drow][s4+2]; ok.w = sk[drow][s4+3];
        *(float4*)(g_Qt + ((size_t)bh * DD + drow) * SS + s0 + s4) = oq;
        *(float4*)(g_Kt + ((size_t)bh * DD + drow) * SS + s0 + s4) = ok;
    }
}

// ---------------- fused causal sigmoid attention (r16, best measured) -------
#define ATTN_SMEM ((8192 + 2*4096 + 4096 + 8192) * 4)   /* 112KB */

__global__ void __launch_bounds__(256, 2) attn_kernel()
{
    extern __shared__ float smx[];
    float* Qs  = smx;                 // [64][128]  [d][q]
    float* Ks0 = smx + 8192;          // [64][64]   [d][k] buf 0
    float* Ks1 = smx + 12288;         // [64][64]   [d][k] buf 1
    float* Vs  = smx + 16384;         // [64][64]   [k][d]
    float* STs = smx + 20480;         // [64][128]  [k][q]  (swizzled)

    const int bh = blockIdx.y;
    const int qb = 15 - blockIdx.x;
    const int tid = threadIdx.x;
    const int tx = tid & 15;
    const int ty = tid >> 4;

#pragma unroll
    for (int i = 0; i < 8; i++) {
        int idx = tid + 256 * i;
        int d = idx >> 5;
        int c = (idx & 31) << 2;
        *(float4*)(Qs + d * 128 + c) =
            *(const float4*)(g_Qt + ((size_t)bh * DD + d) * SS + qb * 128 + c);
    }

#pragma unroll
    for (int i = 0; i < 4; i++) {
        int idx = tid + 256 * i;
        int d = idx >> 4;
        int c = (idx & 15) << 2;
        cp16(Ks0 + d * 64 + c,
             g_Kt + ((size_t)bh * DD + d) * SS + 0 * 64 + c);
    }
    CP_COMMIT();

    u64 o2[4][4];
#pragma unroll
    for (int i = 0; i < 4; i++)
#pragma unroll
        for (int d = 0; d < 4; d++) o2[i][d] = 0ull;

    const int ktmax = 2 * qb + 1;
    for (int kt = 0; kt <= ktmax; kt++) {
        float* Kcur = (kt & 1) ? Ks1 : Ks0;
        float* Knxt = (kt & 1) ? Ks0 : Ks1;

        CP_WAIT0();
        __syncthreads();

#pragma unroll
        for (int i = 0; i < 4; i++) {
            int idx = tid + 256 * i;
            int k = idx >> 4;
            int c = (idx & 15) << 2;
            cp16(Vs + k * 64 + c,
                 g_V + ((size_t)bh * SS + kt * 64 + k) * DD + c);
        }
        CP_COMMIT();

        if (kt < ktmax) {
#pragma unroll
            for (int i = 0; i < 4; i++) {
                int idx = tid + 256 * i;
                int d = idx >> 4;
                int c = (idx & 15) << 2;
                cp16(Knxt + d * 64 + c,
                     g_Kt + ((size_t)bh * DD + d) * SS + (kt + 1) * 64 + c);
            }
        }
        CP_COMMIT();

        u64 s2[4][4];
#pragma unroll
        for (int i = 0; i < 4; i++)
#pragma unroll
            for (int j = 0; j < 4; j++) s2[i][j] = 0ull;

#pragma unroll 4
        for (int kk = 0; kk < 64; kk++) {
            float4 a0 = *(float4*)(Qs + kk * 128 + ty * 8);
            float4 a1 = *(float4*)(Qs + kk * 128 + ty * 8 + 4);
            float4 b0 = *(float4*)(Kcur + kk * 64 + tx * 4);
            u64 ap[4];
            PACK2(ap[0], a0.x, a0.y); PACK2(ap[1], a0.z, a0.w);
            PACK2(ap[2], a1.x, a1.y); PACK2(ap[3], a1.z, a1.w);
            u64 bd[4];
            PACK2(bd[0], b0.x, b0.x); PACK2(bd[1], b0.y, b0.y);
            PACK2(bd[2], b0.z, b0.z); PACK2(bd[3], b0.w, b0.w);
#pragma unroll
            for (int i = 0; i < 4; i++)
#pragma unroll
                for (int j = 0; j < 4; j++)
                    FMA2(s2[i][j], ap[i], bd[j]);
        }

        const bool diagzone = (kt >= 2 * qb);
        const int koff = (kt - 2 * qb) * 64;
#pragma unroll
        for (int j = 0; j < 4; j++) {
            int krow = tx * 4 + j;
#pragma unroll
            for (int i = 0; i < 4; i++) {
                float sa, sb;
                UNPACK2(sa, sb, s2[i][j]);
                float pa = __fdividef(1.f, 1.f + ex2f(-sa));
                float pb = __fdividef(1.f, 1.f + ex2f(-sb));
                if (diagzone) {
                    int qa = ty * 8 + 2 * i;
                    if (koff + krow > qa)     pa = 0.f;
                    if (koff + krow > qa + 1) pb = 0.f;
                }
                int c4s = (ty * 2 + (i >> 1)) ^ tx;
                float2 pv; pv.x = pa; pv.y = pb;
                *(float2*)(STs + krow * 128 + c4s * 4 + (i & 1) * 2) = pv;
            }
        }
        CP_WAIT1G();
        __syncthreads();

#pragma unroll 4
        for (int t = 0; t < 64; t++) {
            int g = (t >> 2) & 15;
            float4 s0 = *(float4*)(STs + t * 128 + ((ty * 2)     ^ g) * 4);
            float4 s1 = *(float4*)(STs + t * 128 + ((ty * 2 + 1) ^ g) * 4);
            float4 vv = *(float4*)(Vs + t * 64 + tx * 4);
            u64 sp[4];
            PACK2(sp[0], s0.x, s0.y); PACK2(sp[1], s0.z, s0.w);
            PACK2(sp[2], s1.x, s1.y); PACK2(sp[3], s1.z, s1.w);
            u64 vd[4];
            PACK2(vd[0], vv.x, vv.x); PACK2(vd[1], vv.y, vv.y);
            PACK2(vd[2], vv.z, vv.z); PACK2(vd[3], vv.w, vv.w);
#pragma unroll
            for (int i = 0; i < 4; i++)
#pragma unroll
                for (int d = 0; d < 4; d++)
                    FMA2(o2[i][d], sp[i], vd[d]);
        }
    }

    const int b = bh / NH;
    const int h = bh % NH;
#pragma unroll
    for (int i = 0; i < 4; i++) {
        int q0 = qb * 128 + ty * 8 + 2 * i;
        float4 r0, r1;
        UNPACK2(r0.x, r1.x, o2[i][0]);
        UNPACK2(r0.y, r1.y, o2[i][1]);
        UNPACK2(r0.z, r1.z, o2[i][2]);
        UNPACK2(r0.w, r1.w, o2[i][3]);
        *(float4*)(g_attn + ((size_t)(b * SS + q0))     * HH + h * DD + tx * 4) = r0;
        *(float4*)(g_attn + ((size_t)(b * SS + q0 + 1)) * HH + h * DD + tx * 4) = r1;
    }
}

// ---------------- LayerNorm + SiLU gate -> transposed into g_AT -------------
__device__ __forceinline__ float block_reduce_sum(float v, float* red)
{
    int lane = threadIdx.x & 31;
    int wid  = threadIdx.x >> 5;
#pragma unroll
    for (int o = 16; o > 0; o >>= 1) v += __shfl_xor_sync(0xffffffffu, v, o);
    if (lane == 0) red[wid] = v;
    __syncthreads();
    float r = (lane < 8) ? red[lane] : 0.f;
    if (wid == 0) {
#pragma unroll
        for (int o = 4; o > 0; o >>= 1) r += __shfl_xor_sync(0xffffffffu, r, o);
        if (lane == 0) red[0] = r;
    }
    __syncthreads();
    float out = red[0];
    __syncthreads();
    return out;
}

__global__ void __launch_bounds__(256) ln_gate_kernel(
    const float* __restrict__ gamma, const float* __restrict__ beta)
{
    __shared__ float sm[HH];
    __shared__ float red[32];
    const int row = blockIdx.x;
    const int tid = threadIdx.x;

    float loc = 0.f;
#pragma unroll
    for (int k = 0; k < 3; k++) {
        int i = tid + k * 256;
        float v = g_attn[(size_t)row * HH + i];
        sm[i] = v;
        loc += v;
    }
    float mu = block_reduce_sum(loc, red) * (1.f / HH);

    float loc2 = 0.f;
#pragma unroll
    for (int k = 0; k < 3; k++) {
        int i = tid + k * 256;
        float d = sm[i] - mu;
        loc2 += d * d;
    }
    float var = block_reduce_sum(loc2, red) * (1.f / HH);
    float rstd = rsqrtf(var + 1e-8f);

#pragma unroll
    for (int k = 0; k < 3; k++) {
        int i = tid + k * 256;
        float ln = (sm[i] - mu) * rstd * gamma[i] + beta[i];
        float u = g_proj[(size_t)row * N4H + i];   // U = first quarter
        float silu = __fdividef(u, 1.f + __expf(-u));
        g_AT[(size_t)i * M_TOT + row] = silu * ln;  // transposed
    }
}

// ---------------- launch ----------------
extern "C" void kernel_launch(void* const* d_in, const int* in_sizes, int n_in,
                              void* d_out, int out_size)
{
    const float* x      = (const float*)d_in[0];
    // d_in[1] = attn_mask (causal tril bool) — structure hardcoded
    const float* W_proj = (const float*)d_in[2];
    const float* b_proj = (const float*)d_in[3];
    const float* gamma  = (const float*)d_in[4];
    const float* beta   = (const float*)d_in[5];
    const float* W_out  = (const float*)d_in[6];
    const float* b_out  = (const float*)d_in[7];
    float* out = (float*)d_out;

    cudaFuncSetAttribute(attn_kernel,
        cudaFuncAttributeMaxDynamicSharedMemorySize, ATTN_SMEM);

    // 1. RoPE tables + A transpose staging
    rope_table_kernel<<<SS, DD>>>();
    transpose_x_kernel<<<dim3(M_TOT/32, HH/32), dim3(32, 8)>>>(x);

    // 2. proj = x @ W_proj + b_proj  (reads g_AT = xT)
    gemm_kernel<<<dim3(N4H/128, M_TOT/128), 256>>>(
        W_proj, b_proj, nullptr, nullptr, N4H, 0);

    // 3. RoPE + transpose into attention layouts
    rope_kernel<<<dim3(SS/64, BB*NH), 256>>>();

    // 4. fused causal sigmoid attention
    attn_kernel<<<dim3(SS/128, BB*NH), 256, ATTN_SMEM>>>();

    // 5. LayerNorm + SiLU(U) gate -> g_AT (transposed; xT dead)
    ln_gate_kernel<<<M_TOT, 256>>>(gamma, beta);

    // 6. out = residual + gated @ W_out + b_out  (reads g_AT = gatedT)
    gemm_kernel<<<dim3(HH/128, M_TOT/128), 256>>>(
        W_out, b_out, x, out, HH, 1);
}